// round 7
// baseline (speedup 1.0000x reference)
#include <cuda_runtime.h>
#include <cuda_bf16.h>
#include <cstdint>

#define N_USER   6144
#define NTOT     12288
#define D        64
#define BATCH    2048
#define NNEG     8192
#define MAXF     2049
#define MAXU     10240
#define UBASE    2176                 // 17 F-tiles * 128
#define SLOTS    (UBASE + MAXU)
#define KT       32                   // K per tile
#define NSPLIT   4
#define KSPL_F   (NTOT / NSPLIT)      // 3072
#define KSPL_U   (N_USER / NSPLIT)    // 1536 (items half only)
#define NTILES   97
#define ASTRIDE  40                   // bf16 units (80 B row) -> conflict-free ldmatrix
#define BSTRIDE  40

// ---- dynamic smem byte offsets ----
#define AH_OFF   0
#define ABUF     10240                // 128*40*2
#define AL_OFF   20480
#define BH_OFF   40960
#define BBUF     5120                 // 64*40*2
#define BL_OFF   51200
#define ROWP_OFF 61440
#define SM_TOTAL 62464

// -------- device scratch --------
__device__ float g_ego[NTOT * D];
__device__ __nv_bfloat16 g_eThi[(size_t)D * NTOT], g_eTlo[(size_t)D * NTOT];
__device__ __nv_bfloat16 g_eMhi[(size_t)D * NTOT], g_eMlo[(size_t)D * NTOT];
__device__ int g_flag[NTOT], g_needed[NTOT];
__device__ int g_listF[MAXF], g_listU[MAXU], g_pos[NTOT];
__device__ int g_cF, g_cU;
__device__ float g_part[NSPLIT][(size_t)SLOTS * D];

__device__ __forceinline__ uint32_t smem_u32(const void* p) {
    uint32_t a;
    asm("{ .reg .u64 t; cvta.to.shared.u64 t, %1; cvt.u32.u64 %0, t; }" : "=r"(a) : "l"(p));
    return a;
}
__device__ __forceinline__ void cp16(uint32_t dst, const void* src) {
    asm volatile("cp.async.ca.shared.global [%0], [%1], 16;" :: "r"(dst), "l"(src));
}
#define CP_COMMIT() asm volatile("cp.async.commit_group;" ::: "memory")
#define CP_WAIT(n)  asm volatile("cp.async.wait_group %0;" :: "n"(n) : "memory")

__device__ __forceinline__ void ldmx4(uint32_t* r, uint32_t addr) {
    asm volatile("ldmatrix.sync.aligned.m8n8.x4.shared.b16 {%0,%1,%2,%3}, [%4];"
                 : "=r"(r[0]), "=r"(r[1]), "=r"(r[2]), "=r"(r[3]) : "r"(addr));
}
__device__ __forceinline__ void mma16816(float* c, const uint32_t* a, const uint32_t* b) {
    asm volatile("mma.sync.aligned.m16n8k16.row.col.f32.bf16.bf16.f32 "
                 "{%0,%1,%2,%3},{%4,%5,%6,%7},{%8,%9},{%0,%1,%2,%3};"
                 : "+f"(c[0]), "+f"(c[1]), "+f"(c[2]), "+f"(c[3])
                 : "r"(a[0]), "r"(a[1]), "r"(a[2]), "r"(a[3]), "r"(b[0]), "r"(b[1]));
}
__device__ __forceinline__ void split2(float2 x, uint32_t& h, uint32_t& l) {
    __nv_bfloat162 hb = __float22bfloat162_rn(x);
    float2 hf = __bfloat1622float2(hb);
    __nv_bfloat162 lb = __float22bfloat162_rn(make_float2(x.x - hf.x, x.y - hf.y));
    h = *(uint32_t*)&hb; l = *(uint32_t*)&lb;
}

// -------- 1. init --------
__global__ void k_init(const float* __restrict__ ue, const float* __restrict__ ie) {
    int r = blockIdx.x, d = threadIdx.x;
    g_ego[r * D + d] = (r < N_USER) ? ue[r * D + d] : ie[(r - N_USER) * D + d];
    if (d == 0) { g_flag[r] = 0; g_needed[r] = 0; }
}

// -------- 2. fused scatter + deterministic compaction + slot map (1 block) --------
__global__ void k_compact(const int* __restrict__ users, const int* __restrict__ pos,
                          const int* __restrict__ neg) {
    __shared__ int warpF[32], warpU[32];
    __shared__ int baseF, baseU;
    int tid = threadIdx.x, lane = tid & 31, wid = tid >> 5;
    // scatter
    if (tid == 0) { g_flag[users[0]] = 1; baseF = 0; baseU = 0; }
    for (int i = tid; i < NNEG; i += 1024) g_needed[N_USER + neg[i]] = 1;
    for (int i = tid; i < BATCH; i += 1024) {
        int rp = N_USER + pos[i];
        g_flag[rp] = 1; g_needed[rp] = 1;
        g_needed[users[i]] = 1;
    }
    __syncthreads();
    // compaction (ascending, deterministic)
    for (int base = 0; base < NTOT; base += 1024) {
        int i = base + tid;
        int f = g_flag[i];
        int u = (!f) && g_needed[i];
        unsigned bf = __ballot_sync(0xFFFFFFFFu, f);
        unsigned bu = __ballot_sync(0xFFFFFFFFu, u);
        if (lane == 0) { warpF[wid] = __popc(bf); warpU[wid] = __popc(bu); }
        __syncthreads();
        int offF = baseF, offU = baseU;
        for (int k = 0; k < wid; ++k) { offF += warpF[k]; offU += warpU[k]; }
        if (f) {
            int j = offF + __popc(bf & ((1u << lane) - 1u));
            g_listF[j] = i; g_pos[i] = j;
        }
        if (u) {
            int j = offU + __popc(bu & ((1u << lane) - 1u));
            g_listU[j] = i; g_pos[i] = UBASE + j;
        }
        __syncthreads();
        if (tid == 0)
            for (int k = 0; k < 32; ++k) { baseF += warpF[k]; baseU += warpU[k]; }
        __syncthreads();
    }
    if (tid == 0) { g_cF = baseF; g_cU = baseU; }
}

// -------- 3. tiled transpose: ego -> bf16 hi/lo T (masked copies upper half only) --------
__global__ void k_prepT() {
    __shared__ float tile[64][65];
    __shared__ int sflag[64];
    int k0 = blockIdx.x * 64;
    int tid = threadIdx.x;
    if (tid < 64) sflag[tid] = g_flag[k0 + tid];
#pragma unroll
    for (int i = 0; i < 16; ++i) {
        int e = tid + i * 256;
        int k = e >> 6, n = e & 63;
        tile[k][n] = g_ego[(size_t)(k0 + k) * D + n];
    }
    __syncthreads();
    bool upper = (k0 >= N_USER);
#pragma unroll
    for (int i = 0; i < 16; ++i) {
        int e = tid + i * 256;
        int n = e >> 6, kk = e & 63;
        float x = tile[kk][n];
        __nv_bfloat16 h = __float2bfloat16(x);
        float hf = __bfloat162float(h);
        __nv_bfloat16 l = __float2bfloat16(x - hf);
        size_t o = (size_t)n * NTOT + k0 + kk;
        g_eThi[o] = h; g_eTlo[o] = l;
        if (upper) {
            bool f = sflag[kk] != 0;
            __nv_bfloat16 z = __float2bfloat16(0.f);
            g_eMhi[o] = f ? h : z;
            g_eMlo[o] = f ? l : z;
        }
    }
}

// -------- 4. main GEMM: fully pipelined (A reg-prefetch -> smem, B cp.async) --------
__global__ void __launch_bounds__(256, 2) k_main(const float* __restrict__ adj) {
    extern __shared__ char sm[];
    uint32_t smb = smem_u32(sm);
    const float** sRow = (const float**)(sm + ROWP_OFF);

    int tid = threadIdx.x, wid = tid >> 5, lane = tid & 31;
    int cF = g_cF, cU = g_cU;
    int nTF = (cF + 127) >> 7;
    int t = blockIdx.x, split = blockIdx.y;

    int slotBase, j0, cnt, nkt;
    size_t kbase;
    const int* list;
    const __nv_bfloat16 *bh, *bl;
    if (t < nTF) {
        j0 = t * 128; slotBase = j0; list = g_listF; cnt = cF;
        bh = g_eThi; bl = g_eTlo;
        kbase = (size_t)split * KSPL_F; nkt = KSPL_F / KT;     // 96
    } else {
        int u = t - nTF;
        if (u * 128 >= cU) return;
        j0 = u * 128; slotBase = UBASE + j0; list = g_listU; cnt = cU;
        bh = g_eMhi; bl = g_eMlo;
        kbase = (size_t)N_USER + (size_t)split * KSPL_U; nkt = KSPL_U / KT;  // 48
    }

    if (tid < 128) {
        int j = j0 + tid; if (j >= cnt) j = cnt - 1;
        sRow[tid] = adj + (size_t)list[j] * NTOT + kbase;
    }
    __syncthreads();

    // A staging: thread -> (row = tid&127, khalf = tid>>7), 16 floats per kt
    int arow = tid & 127, ahalf = tid >> 7;
    const float* aptr = sRow[arow] + ahalf * 16;
    uint32_t aStsH = smb + AH_OFF + (uint32_t)(arow * ASTRIDE + ahalf * 16) * 2;
    uint32_t aStsL = aStsH + (AL_OFF - AH_OFF);

    // B staging via cp.async: thread -> (n = tid>>2, chunk = tid&3)
    int bn = tid >> 2, bc = tid & 3;
    const __nv_bfloat16* bsrcH = bh + kbase + (size_t)bn * NTOT + bc * 8;
    const __nv_bfloat16* bsrcL = bl + kbase + (size_t)bn * NTOT + bc * 8;
    uint32_t bDstH = smb + BH_OFF + (uint32_t)(bn * BSTRIDE + bc * 8) * 2;
    uint32_t bDstL = bDstH + (BL_OFF - BH_OFF);

    // ldmatrix lane offsets
    uint32_t aLm = (uint32_t)(((wid * 16 + (lane & 15)) * ASTRIDE + (lane >> 4) * 8) * 2);
    uint32_t bLm = (uint32_t)((((lane & 7) + ((lane >> 4) << 3)) * BSTRIDE + ((lane >> 3) & 1) * 8) * 2);

    float acc[8][4];
#pragma unroll
    for (int nb = 0; nb < 8; ++nb)
#pragma unroll
        for (int i = 0; i < 4; ++i) acc[nb][i] = 0.f;

    // prologue: A(0) -> regs, B(0) -> cp.async buf0
    float rA[16];
#pragma unroll
    for (int i = 0; i < 4; ++i) *(float4*)&rA[i * 4] = *(const float4*)(aptr + i * 4);
    cp16(bDstH, bsrcH); cp16(bDstL, bsrcL); CP_COMMIT();

    for (int kt = 0; kt < nkt; ++kt) {
        int buf = kt & 1;
        // convert + STS A(kt)
        {
            uint32_t h[8], l[8];
#pragma unroll
            for (int j = 0; j < 8; ++j)
                split2(make_float2(rA[2 * j], rA[2 * j + 1]), h[j], l[j]);
            uint32_t dh = aStsH + buf * ABUF, dl = aStsL + buf * ABUF;
            *(uint4*)(sm + (dh - smb))      = *(uint4*)&h[0];
            *(uint4*)(sm + (dh - smb) + 16) = *(uint4*)&h[4];
            *(uint4*)(sm + (dl - smb))      = *(uint4*)&l[0];
            *(uint4*)(sm + (dl - smb) + 16) = *(uint4*)&l[4];
        }
        if (kt + 1 < nkt) {
            const float* ap = aptr + (kt + 1) * KT;
#pragma unroll
            for (int i = 0; i < 4; ++i) *(float4*)&rA[i * 4] = *(const float4*)(ap + i * 4);
            int nb2 = (kt + 1) & 1;
            size_t ko = (size_t)(kt + 1) * KT;
            cp16(bDstH + nb2 * BBUF, bsrcH + ko);
            cp16(bDstL + nb2 * BBUF, bsrcL + ko);
            CP_COMMIT();
            CP_WAIT(1);
        } else {
            CP_WAIT(0);
        }
        __syncthreads();

        uint32_t ah_base = smb + AH_OFF + buf * ABUF + aLm;
        uint32_t al_base = ah_base + (AL_OFF - AH_OFF);
        uint32_t bh_base = smb + BH_OFF + buf * BBUF + bLm;
        uint32_t bl_base = bh_base + (BL_OFF - BH_OFF);

#pragma unroll
        for (int ks = 0; ks < 2; ++ks) {
            uint32_t ahf[4], alf[4];
            ldmx4(ahf, ah_base + ks * 32);
            ldmx4(alf, al_base + ks * 32);
            uint32_t bhf[8][2], blf[8][2];
#pragma unroll
            for (int p = 0; p < 4; ++p) {
                uint32_t r[4];
                uint32_t o = (uint32_t)(p * 16 * BSTRIDE * 2 + ks * 32);
                ldmx4(r, bh_base + o);
                bhf[p * 2][0] = r[0]; bhf[p * 2][1] = r[1];
                bhf[p * 2 + 1][0] = r[2]; bhf[p * 2 + 1][1] = r[3];
                ldmx4(r, bl_base + o);
                blf[p * 2][0] = r[0]; blf[p * 2][1] = r[1];
                blf[p * 2 + 1][0] = r[2]; blf[p * 2 + 1][1] = r[3];
            }
#pragma unroll
            for (int nb = 0; nb < 8; ++nb) {
                mma16816(acc[nb], ahf, bhf[nb]);
                mma16816(acc[nb], ahf, blf[nb]);
                mma16816(acc[nb], alf, bhf[nb]);
            }
        }
        __syncthreads();
    }

    float* dst = g_part[split];
    int r0 = slotBase + wid * 16 + (lane >> 2);
#pragma unroll
    for (int nb = 0; nb < 8; ++nb) {
        int col = nb * 8 + (lane & 3) * 2;
        *(float2*)(dst + (size_t)r0 * D + col)       = make_float2(acc[nb][0], acc[nb][1]);
        *(float2*)(dst + (size_t)(r0 + 8) * D + col) = make_float2(acc[nb][2], acc[nb][3]);
    }
}

// -------- 5. gather + deterministic reduction + rank-1 user column for U rows --------
__global__ void k_gather(const float* __restrict__ adj,
                         const int* __restrict__ users, const int* __restrict__ pos,
                         const int* __restrict__ neg, float* __restrict__ out) {
    int t = blockIdx.x * 256 + threadIdx.x;
    int q = t >> 6, d = t & 63;
    int r;
    if (q < BATCH)          r = users[q];
    else if (q < 2 * BATCH) r = N_USER + pos[q - BATCH];
    else                    r = N_USER + neg[q - 2 * BATCH];
    int p = g_pos[r];
    float s = g_part[0][(size_t)p * D + d] + g_part[1][(size_t)p * D + d]
            + g_part[2][(size_t)p * D + d] + g_part[3][(size_t)p * D + d];
    if (p >= UBASE) {
        int u0 = users[0];
        s += adj[(size_t)r * NTOT + u0] * g_ego[(size_t)u0 * D + d];
    }
    out[t] = 0.25f * (g_ego[(size_t)r * D + d] + 3.0f * s);
}

extern "C" void kernel_launch(void* const* d_in, const int* in_sizes, int n_in,
                              void* d_out, int out_size) {
    const float* adj   = (const float*)d_in[0];
    const float* ue    = (const float*)d_in[1];
    const float* ie    = (const float*)d_in[2];
    const int*   users = (const int*)d_in[3];
    const int*   pos   = (const int*)d_in[4];
    const int*   neg   = (const int*)d_in[5];
    float*       out   = (float*)d_out;

    cudaFuncSetAttribute(k_main, cudaFuncAttributeMaxDynamicSharedMemorySize, SM_TOTAL);

    k_init<<<NTOT, D>>>(ue, ie);
    k_compact<<<1, 1024>>>(users, pos, neg);
    k_prepT<<<NTOT / 64, 256>>>();
    dim3 gM(NTILES, NSPLIT);
    k_main<<<gM, 256, SM_TOTAL>>>(adj);
    k_gather<<<(6 * BATCH * D) / 256, 256>>>(adj, users, pos, neg, out);
}

// round 8
// speedup vs baseline: 1.3368x; 1.3368x over previous
#include <cuda_runtime.h>
#include <cuda_bf16.h>
#include <cstdint>

#define N_USER   6144
#define NTOT     12288
#define D        64
#define BATCH    2048
#define NNEG     8192
#define MAXF     2049
#define MAXU     10240
#define UBASE    2176                 // 17 F-tiles * 128
#define SLOTS    (UBASE + MAXU)
#define KT       32                   // K per stage
#define NSPLIT   4
#define KSPL_F   (NTOT / NSPLIT)      // 3072 -> 96 kt
#define KSPL_U   (N_USER / NSPLIT)    // 1536 -> 48 kt
#define NTILES   97
#define NSTAGE   3
#define ASTR     40                   // fp32 units, conflict-free LDS
#define BSTR     40                   // bf16 units, conflict-free ldmatrix

// ---- dynamic smem byte offsets ----
#define A_OFF    0
#define ASTAGE   20480                // 128*40*4
#define BH_OFF   (ASTAGE * NSTAGE)            // 61440
#define BSTAGE   5120                 // 64*40*2
#define BL_OFF   (BH_OFF + BSTAGE * NSTAGE)   // 76800
#define ROWP_OFF (BL_OFF + BSTAGE * NSTAGE)   // 92160
#define SM_TOTAL (ROWP_OFF + 128 * 8)         // 93184

// -------- device scratch --------
__device__ float g_ego[NTOT * D];
__device__ __nv_bfloat16 g_eThi[(size_t)D * NTOT], g_eTlo[(size_t)D * NTOT];
__device__ __nv_bfloat16 g_eMhi[(size_t)D * NTOT], g_eMlo[(size_t)D * NTOT];
__device__ int g_flag[NTOT], g_needed[NTOT];
__device__ int g_listF[MAXF], g_listU[MAXU], g_pos[NTOT];
__device__ int g_cF, g_cU;
__device__ float g_part[NSPLIT][(size_t)SLOTS * D];

__device__ __forceinline__ uint32_t smem_u32(const void* p) {
    uint32_t a;
    asm("{ .reg .u64 t; cvta.to.shared.u64 t, %1; cvt.u32.u64 %0, t; }" : "=r"(a) : "l"(p));
    return a;
}
__device__ __forceinline__ void cp16(uint32_t dst, const void* src) {
    asm volatile("cp.async.ca.shared.global [%0], [%1], 16;" :: "r"(dst), "l"(src));
}
#define CP_COMMIT() asm volatile("cp.async.commit_group;" ::: "memory")
#define CP_WAIT(n)  asm volatile("cp.async.wait_group %0;" :: "n"(n) : "memory")

__device__ __forceinline__ void ldmx4(uint32_t* r, uint32_t addr) {
    asm volatile("ldmatrix.sync.aligned.m8n8.x4.shared.b16 {%0,%1,%2,%3}, [%4];"
                 : "=r"(r[0]), "=r"(r[1]), "=r"(r[2]), "=r"(r[3]) : "r"(addr));
}
__device__ __forceinline__ void mma16816(float* c, const uint32_t* a, const uint32_t* b) {
    asm volatile("mma.sync.aligned.m16n8k16.row.col.f32.bf16.bf16.f32 "
                 "{%0,%1,%2,%3},{%4,%5,%6,%7},{%8,%9},{%0,%1,%2,%3};"
                 : "+f"(c[0]), "+f"(c[1]), "+f"(c[2]), "+f"(c[3])
                 : "r"(a[0]), "r"(a[1]), "r"(a[2]), "r"(a[3]), "r"(b[0]), "r"(b[1]));
}
__device__ __forceinline__ void split2(float2 x, uint32_t& h, uint32_t& l) {
    __nv_bfloat162 hb = __float22bfloat162_rn(x);
    float2 hf = __bfloat1622float2(hb);
    __nv_bfloat162 lb = __float22bfloat162_rn(make_float2(x.x - hf.x, x.y - hf.y));
    h = *(uint32_t*)&hb; l = *(uint32_t*)&lb;
}

// -------- 1. init --------
__global__ void k_init(const float* __restrict__ ue, const float* __restrict__ ie) {
    int r = blockIdx.x, d = threadIdx.x;
    g_ego[r * D + d] = (r < N_USER) ? ue[r * D + d] : ie[(r - N_USER) * D + d];
    if (d == 0) { g_flag[r] = 0; g_needed[r] = 0; }
}

// -------- 2. fused scatter + deterministic compaction + slot map --------
__global__ void k_compact(const int* __restrict__ users, const int* __restrict__ pos,
                          const int* __restrict__ neg) {
    __shared__ int warpF[32], warpU[32];
    __shared__ int baseF, baseU;
    int tid = threadIdx.x, lane = tid & 31, wid = tid >> 5;
    if (tid == 0) { g_flag[users[0]] = 1; baseF = 0; baseU = 0; }
    for (int i = tid; i < NNEG; i += 1024) g_needed[N_USER + neg[i]] = 1;
    for (int i = tid; i < BATCH; i += 1024) {
        int rp = N_USER + pos[i];
        g_flag[rp] = 1; g_needed[rp] = 1;
        g_needed[users[i]] = 1;
    }
    __syncthreads();
    for (int base = 0; base < NTOT; base += 1024) {
        int i = base + tid;
        int f = g_flag[i];
        int u = (!f) && g_needed[i];
        unsigned bf = __ballot_sync(0xFFFFFFFFu, f);
        unsigned bu = __ballot_sync(0xFFFFFFFFu, u);
        if (lane == 0) { warpF[wid] = __popc(bf); warpU[wid] = __popc(bu); }
        __syncthreads();
        int offF = baseF, offU = baseU;
        for (int k = 0; k < wid; ++k) { offF += warpF[k]; offU += warpU[k]; }
        if (f) {
            int j = offF + __popc(bf & ((1u << lane) - 1u));
            g_listF[j] = i; g_pos[i] = j;
        }
        if (u) {
            int j = offU + __popc(bu & ((1u << lane) - 1u));
            g_listU[j] = i; g_pos[i] = UBASE + j;
        }
        __syncthreads();
        if (tid == 0)
            for (int k = 0; k < 32; ++k) { baseF += warpF[k]; baseU += warpU[k]; }
        __syncthreads();
    }
    if (tid == 0) { g_cF = baseF; g_cU = baseU; }
}

// -------- 3. tiled transpose: ego -> bf16 hi/lo T --------
__global__ void k_prepT() {
    __shared__ float tile[64][65];
    __shared__ int sflag[64];
    int k0 = blockIdx.x * 64;
    int tid = threadIdx.x;
    if (tid < 64) sflag[tid] = g_flag[k0 + tid];
#pragma unroll
    for (int i = 0; i < 16; ++i) {
        int e = tid + i * 256;
        int k = e >> 6, n = e & 63;
        tile[k][n] = g_ego[(size_t)(k0 + k) * D + n];
    }
    __syncthreads();
    bool upper = (k0 >= N_USER);
#pragma unroll
    for (int i = 0; i < 16; ++i) {
        int e = tid + i * 256;
        int n = e >> 6, kk = e & 63;
        float x = tile[kk][n];
        __nv_bfloat16 h = __float2bfloat16(x);
        float hf = __bfloat162float(h);
        __nv_bfloat16 l = __float2bfloat16(x - hf);
        size_t o = (size_t)n * NTOT + k0 + kk;
        g_eThi[o] = h; g_eTlo[o] = l;
        if (upper) {
            bool f = sflag[kk] != 0;
            __nv_bfloat16 z = __float2bfloat16(0.f);
            g_eMhi[o] = f ? h : z;
            g_eMlo[o] = f ? l : z;
        }
    }
}

// -------- 4. main GEMM: 3-stage cp.async pipeline (A fp32 + B bf16 hi/lo) --------
__global__ void __launch_bounds__(256, 2) k_main(const float* __restrict__ adj) {
    extern __shared__ char sm[];
    uint32_t smb = smem_u32(sm);
    const float** sRow = (const float**)(sm + ROWP_OFF);

    int tid = threadIdx.x, wid = tid >> 5, lane = tid & 31;
    int cF = g_cF, cU = g_cU;
    int nTF = (cF + 127) >> 7;
    int t = blockIdx.x, split = blockIdx.y;

    int slotBase, j0, cnt, nkt;
    size_t kbase;
    const int* list;
    const __nv_bfloat16 *bh, *bl;
    if (t < nTF) {
        j0 = t * 128; slotBase = j0; list = g_listF; cnt = cF;
        bh = g_eThi; bl = g_eTlo;
        kbase = (size_t)split * KSPL_F; nkt = KSPL_F / KT;     // 96
    } else {
        int u = t - nTF;
        if (u * 128 >= cU) return;
        j0 = u * 128; slotBase = UBASE + j0; list = g_listU; cnt = cU;
        bh = g_eMhi; bl = g_eMlo;
        kbase = (size_t)N_USER + (size_t)split * KSPL_U; nkt = KSPL_U / KT;  // 48
    }

    if (tid < 128) {
        int j = j0 + tid; if (j >= cnt) j = cnt - 1;
        sRow[tid] = adj + (size_t)list[j] * NTOT + kbase;
    }
    __syncthreads();

    // ---- A staging map: thread covers rows r0+32j (j<4), 16B chunk ch ----
    int r0s = tid >> 3, chs = tid & 7;
    const float* apj[4];
#pragma unroll
    for (int j = 0; j < 4; ++j) apj[j] = sRow[r0s + 32 * j] + chs * 4;
    uint32_t aDst = smb + A_OFF + (uint32_t)(r0s * ASTR + chs * 4) * 4;

    // ---- B staging map: n = tid>>2, chunk bc = tid&3 ----
    int bn = tid >> 2, bc = tid & 3;
    const __nv_bfloat16* bsrcH = bh + kbase + (size_t)bn * NTOT + bc * 8;
    const __nv_bfloat16* bsrcL = bl + kbase + (size_t)bn * NTOT + bc * 8;
    uint32_t bDstH = smb + BH_OFF + (uint32_t)(bn * BSTR + bc * 8) * 2;
    uint32_t bDstL = smb + BL_OFF + (uint32_t)(bn * BSTR + bc * 8) * 2;

    // ---- compute-side addressing ----
    const float* aBase = (const float*)(sm + A_OFF);
    int frow0 = wid * 16 + (lane >> 2);
    const float* aR0 = aBase + frow0 * ASTR + (lane & 3) * 2;
    const float* aR1 = aR0 + 8 * ASTR;
    uint32_t bLm = (uint32_t)((((lane & 7) + ((lane >> 4) << 3)) * BSTR + ((lane >> 3) & 1) * 8) * 2);

    float acc[8][4];
#pragma unroll
    for (int nb = 0; nb < 8; ++nb)
#pragma unroll
        for (int i = 0; i < 4; ++i) acc[nb][i] = 0.f;

    // ---- prologue: stages 0,1 ----
#pragma unroll
    for (int s = 0; s < 2; ++s) {
        uint32_t ad = aDst + s * ASTAGE;
        size_t ko = (size_t)s * KT;
#pragma unroll
        for (int j = 0; j < 4; ++j) cp16(ad + j * (32 * ASTR * 4), apj[j] + ko);
        cp16(bDstH + s * BSTAGE, bsrcH + ko);
        cp16(bDstL + s * BSTAGE, bsrcL + ko);
        CP_COMMIT();
    }

    for (int kt = 0; kt < nkt; ++kt) {
        int buf = kt % NSTAGE;
        CP_WAIT(1);
        __syncthreads();
        if (kt + 2 < nkt) {
            int s = (kt + 2) % NSTAGE;
            uint32_t ad = aDst + s * ASTAGE;
            size_t ko = (size_t)(kt + 2) * KT;
#pragma unroll
            for (int j = 0; j < 4; ++j) cp16(ad + j * (32 * ASTR * 4), apj[j] + ko);
            cp16(bDstH + s * BSTAGE, bsrcH + ko);
            cp16(bDstL + s * BSTAGE, bsrcL + ko);
        }
        CP_COMMIT();

        const float* a0 = aR0 + buf * (ASTAGE / 4);
        const float* a1 = aR1 + buf * (ASTAGE / 4);
        uint32_t bh_base = smb + BH_OFF + buf * BSTAGE + bLm;
        uint32_t bl_base = smb + BL_OFF + buf * BSTAGE + bLm;

#pragma unroll
        for (int ks = 0; ks < 2; ++ks) {
            int ko = ks * 16;
            float2 x0 = *(const float2*)(a0 + ko);
            float2 x1 = *(const float2*)(a1 + ko);
            float2 x2 = *(const float2*)(a0 + ko + 8);
            float2 x3 = *(const float2*)(a1 + ko + 8);
            uint32_t ahf[4], alf[4];
            split2(x0, ahf[0], alf[0]);
            split2(x1, ahf[1], alf[1]);
            split2(x2, ahf[2], alf[2]);
            split2(x3, ahf[3], alf[3]);

            uint32_t bhf[8][2], blf[8][2];
#pragma unroll
            for (int p = 0; p < 4; ++p) {
                uint32_t r[4];
                uint32_t o = (uint32_t)(p * 16 * BSTR * 2 + ks * 32);
                ldmx4(r, bh_base + o);
                bhf[p * 2][0] = r[0]; bhf[p * 2][1] = r[1];
                bhf[p * 2 + 1][0] = r[2]; bhf[p * 2 + 1][1] = r[3];
                ldmx4(r, bl_base + o);
                blf[p * 2][0] = r[0]; blf[p * 2][1] = r[1];
                blf[p * 2 + 1][0] = r[2]; blf[p * 2 + 1][1] = r[3];
            }
#pragma unroll
            for (int nb = 0; nb < 8; ++nb) {
                mma16816(acc[nb], ahf, bhf[nb]);
                mma16816(acc[nb], ahf, blf[nb]);
                mma16816(acc[nb], alf, bhf[nb]);
            }
        }
    }

    float* dst = g_part[split];
    int r0 = slotBase + wid * 16 + (lane >> 2);
#pragma unroll
    for (int nb = 0; nb < 8; ++nb) {
        int col = nb * 8 + (lane & 3) * 2;
        *(float2*)(dst + (size_t)r0 * D + col)       = make_float2(acc[nb][0], acc[nb][1]);
        *(float2*)(dst + (size_t)(r0 + 8) * D + col) = make_float2(acc[nb][2], acc[nb][3]);
    }
}

// -------- 5. gather + deterministic reduction + rank-1 user column for U rows --------
__global__ void k_gather(const float* __restrict__ adj,
                         const int* __restrict__ users, const int* __restrict__ pos,
                         const int* __restrict__ neg, float* __restrict__ out) {
    int t = blockIdx.x * 256 + threadIdx.x;
    int q = t >> 6, d = t & 63;
    int r;
    if (q < BATCH)          r = users[q];
    else if (q < 2 * BATCH) r = N_USER + pos[q - BATCH];
    else                    r = N_USER + neg[q - 2 * BATCH];
    int p = g_pos[r];
    float s = g_part[0][(size_t)p * D + d] + g_part[1][(size_t)p * D + d]
            + g_part[2][(size_t)p * D + d] + g_part[3][(size_t)p * D + d];
    if (p >= UBASE) {
        int u0 = users[0];
        s += adj[(size_t)r * NTOT + u0] * g_ego[(size_t)u0 * D + d];
    }
    out[t] = 0.25f * (g_ego[(size_t)r * D + d] + 3.0f * s);
}

extern "C" void kernel_launch(void* const* d_in, const int* in_sizes, int n_in,
                              void* d_out, int out_size) {
    const float* adj   = (const float*)d_in[0];
    const float* ue    = (const float*)d_in[1];
    const float* ie    = (const float*)d_in[2];
    const int*   users = (const int*)d_in[3];
    const int*   pos   = (const int*)d_in[4];
    const int*   neg   = (const int*)d_in[5];
    float*       out   = (float*)d_out;

    cudaFuncSetAttribute(k_main, cudaFuncAttributeMaxDynamicSharedMemorySize, SM_TOTAL);

    k_init<<<NTOT, D>>>(ue, ie);
    k_compact<<<1, 1024>>>(users, pos, neg);
    k_prepT<<<NTOT / 64, 256>>>();
    dim3 gM(NTILES, NSPLIT);
    k_main<<<gM, 256, SM_TOTAL>>>(adj);
    k_gather<<<(6 * BATCH * D) / 256, 256>>>(adj, users, pos, neg, out);
}

// round 9
// speedup vs baseline: 1.5748x; 1.1780x over previous
#include <cuda_runtime.h>
#include <cuda_bf16.h>
#include <cstdint>

#define N_USER   6144
#define NTOT     12288
#define D        64
#define BATCH    2048
#define NNEG     8192
#define MAXF     2049
#define MAXU     10240
#define UBASE    2176                 // 17 F-tiles * 128
#define SLOTS    (UBASE + MAXU)
#define KT       32                   // K per stage
#define NSPF     32                   // F splits: 12288/32 = 384 K each
#define NSPU     16                   // U splits: 6144/16  = 384 K each
#define KSPL     384
#define NKT      12                   // 384/32
#define F_ITEMS  (17 * NSPF)          // 544
#define U_ITEMS  (80 * NSPU)          // 1280
#define NSTAGE   3
#define ASTR     40                   // fp32 units, conflict-free LDS
#define BSTR     40                   // bf16 units, conflict-free ldmatrix

// ---- dynamic smem byte offsets ----
#define A_OFF    0
#define ASTAGE   20480                // 128*40*4
#define BH_OFF   (ASTAGE * NSTAGE)            // 61440
#define BSTAGE   5120                 // 64*40*2
#define BL_OFF   (BH_OFF + BSTAGE * NSTAGE)   // 76800
#define ROWP_OFF (BL_OFF + BSTAGE * NSTAGE)   // 92160
#define SM_TOTAL (ROWP_OFF + 128 * 8)         // 93184

// -------- device scratch --------
__device__ float g_ego[NTOT * D];
__device__ __nv_bfloat16 g_eThi[(size_t)D * NTOT], g_eTlo[(size_t)D * NTOT];
__device__ __nv_bfloat16 g_eMhi[(size_t)D * NTOT], g_eMlo[(size_t)D * NTOT];
__device__ int g_flag[NTOT], g_needed[NTOT];
__device__ int g_listF[MAXF], g_listU[MAXU], g_pos[NTOT];
__device__ int g_cF, g_cU;
__device__ float g_part[NSPF][(size_t)SLOTS * D];

__device__ __forceinline__ uint32_t smem_u32(const void* p) {
    uint32_t a;
    asm("{ .reg .u64 t; cvta.to.shared.u64 t, %1; cvt.u32.u64 %0, t; }" : "=r"(a) : "l"(p));
    return a;
}
__device__ __forceinline__ void cp16(uint32_t dst, const void* src) {
    asm volatile("cp.async.ca.shared.global [%0], [%1], 16;" :: "r"(dst), "l"(src));
}
#define CP_COMMIT() asm volatile("cp.async.commit_group;" ::: "memory")
#define CP_WAIT(n)  asm volatile("cp.async.wait_group %0;" :: "n"(n) : "memory")

__device__ __forceinline__ void ldmx4(uint32_t* r, uint32_t addr) {
    asm volatile("ldmatrix.sync.aligned.m8n8.x4.shared.b16 {%0,%1,%2,%3}, [%4];"
                 : "=r"(r[0]), "=r"(r[1]), "=r"(r[2]), "=r"(r[3]) : "r"(addr));
}
__device__ __forceinline__ void mma16816(float* c, const uint32_t* a, const uint32_t* b) {
    asm volatile("mma.sync.aligned.m16n8k16.row.col.f32.bf16.bf16.f32 "
                 "{%0,%1,%2,%3},{%4,%5,%6,%7},{%8,%9},{%0,%1,%2,%3};"
                 : "+f"(c[0]), "+f"(c[1]), "+f"(c[2]), "+f"(c[3])
                 : "r"(a[0]), "r"(a[1]), "r"(a[2]), "r"(a[3]), "r"(b[0]), "r"(b[1]));
}
__device__ __forceinline__ void split2(float2 x, uint32_t& h, uint32_t& l) {
    __nv_bfloat162 hb = __float22bfloat162_rn(x);
    float2 hf = __bfloat1622float2(hb);
    __nv_bfloat162 lb = __float22bfloat162_rn(make_float2(x.x - hf.x, x.y - hf.y));
    h = *(uint32_t*)&hb; l = *(uint32_t*)&lb;
}

// -------- 1. init --------
__global__ void k_init(const float* __restrict__ ue, const float* __restrict__ ie) {
    int r = blockIdx.x, d = threadIdx.x;
    g_ego[r * D + d] = (r < N_USER) ? ue[r * D + d] : ie[(r - N_USER) * D + d];
    if (d == 0) { g_flag[r] = 0; g_needed[r] = 0; }
}

// -------- 2. fused scatter + deterministic compaction + slot map --------
__global__ void k_compact(const int* __restrict__ users, const int* __restrict__ pos,
                          const int* __restrict__ neg) {
    __shared__ int warpF[32], warpU[32];
    __shared__ int baseF, baseU;
    int tid = threadIdx.x, lane = tid & 31, wid = tid >> 5;
    if (tid == 0) { g_flag[users[0]] = 1; baseF = 0; baseU = 0; }
    for (int i = tid; i < NNEG; i += 1024) g_needed[N_USER + neg[i]] = 1;
    for (int i = tid; i < BATCH; i += 1024) {
        int rp = N_USER + pos[i];
        g_flag[rp] = 1; g_needed[rp] = 1;
        g_needed[users[i]] = 1;
    }
    __syncthreads();
    for (int base = 0; base < NTOT; base += 1024) {
        int i = base + tid;
        int f = g_flag[i];
        int u = (!f) && g_needed[i];
        unsigned bf = __ballot_sync(0xFFFFFFFFu, f);
        unsigned bu = __ballot_sync(0xFFFFFFFFu, u);
        if (lane == 0) { warpF[wid] = __popc(bf); warpU[wid] = __popc(bu); }
        __syncthreads();
        int offF = baseF, offU = baseU;
        for (int k = 0; k < wid; ++k) { offF += warpF[k]; offU += warpU[k]; }
        if (f) {
            int j = offF + __popc(bf & ((1u << lane) - 1u));
            g_listF[j] = i; g_pos[i] = j;
        }
        if (u) {
            int j = offU + __popc(bu & ((1u << lane) - 1u));
            g_listU[j] = i; g_pos[i] = UBASE + j;
        }
        __syncthreads();
        if (tid == 0)
            for (int k = 0; k < 32; ++k) { baseF += warpF[k]; baseU += warpU[k]; }
        __syncthreads();
    }
    if (tid == 0) { g_cF = baseF; g_cU = baseU; }
}

// -------- 3. tiled transpose: ego -> bf16 hi/lo T --------
__global__ void k_prepT() {
    __shared__ float tile[64][65];
    __shared__ int sflag[64];
    int k0 = blockIdx.x * 64;
    int tid = threadIdx.x;
    if (tid < 64) sflag[tid] = g_flag[k0 + tid];
#pragma unroll
    for (int i = 0; i < 16; ++i) {
        int e = tid + i * 256;
        int k = e >> 6, n = e & 63;
        tile[k][n] = g_ego[(size_t)(k0 + k) * D + n];
    }
    __syncthreads();
    bool upper = (k0 >= N_USER);
#pragma unroll
    for (int i = 0; i < 16; ++i) {
        int e = tid + i * 256;
        int n = e >> 6, kk = e & 63;
        float x = tile[kk][n];
        __nv_bfloat16 h = __float2bfloat16(x);
        float hf = __bfloat162float(h);
        __nv_bfloat16 l = __float2bfloat16(x - hf);
        size_t o = (size_t)n * NTOT + k0 + kk;
        g_eThi[o] = h; g_eTlo[o] = l;
        if (upper) {
            bool f = sflag[kk] != 0;
            __nv_bfloat16 z = __float2bfloat16(0.f);
            g_eMhi[o] = f ? h : z;
            g_eMlo[o] = f ? l : z;
        }
    }
}

// -------- 4. main GEMM: uniform 12-kt items, 3-stage cp.async pipeline --------
__global__ void __launch_bounds__(256, 2) k_main(const float* __restrict__ adj) {
    extern __shared__ char sm[];
    uint32_t smb = smem_u32(sm);
    const float** sRow = (const float**)(sm + ROWP_OFF);

    int tid = threadIdx.x, wid = tid >> 5, lane = tid & 31;
    int cF = g_cF, cU = g_cU;
    int bx = blockIdx.x;

    int slotBase, j0, cnt, split;
    size_t kbase;
    const int* list;
    const __nv_bfloat16 *bh, *bl;
    if (bx < F_ITEMS) {
        int tile = bx >> 5; split = bx & (NSPF - 1);
        if (tile * 128 >= cF) return;
        j0 = tile * 128; slotBase = j0; list = g_listF; cnt = cF;
        bh = g_eThi; bl = g_eTlo;
        kbase = (size_t)split * KSPL;
    } else {
        int u = bx - F_ITEMS;
        int tile = u >> 4; split = u & (NSPU - 1);
        if (tile * 128 >= cU) return;
        j0 = tile * 128; slotBase = UBASE + j0; list = g_listU; cnt = cU;
        bh = g_eMhi; bl = g_eMlo;
        kbase = (size_t)N_USER + (size_t)split * KSPL;
    }

    if (tid < 128) {
        int j = j0 + tid; if (j >= cnt) j = cnt - 1;
        sRow[tid] = adj + (size_t)list[j] * NTOT + kbase;
    }
    __syncthreads();

    // ---- A staging map: thread covers rows r0+32j (j<4), 16B chunk ch ----
    int r0s = tid >> 3, chs = tid & 7;
    const float* apj[4];
#pragma unroll
    for (int j = 0; j < 4; ++j) apj[j] = sRow[r0s + 32 * j] + chs * 4;
    uint32_t aDst = smb + A_OFF + (uint32_t)(r0s * ASTR + chs * 4) * 4;

    // ---- B staging map: n = tid>>2, chunk bc = tid&3 ----
    int bn = tid >> 2, bc = tid & 3;
    const __nv_bfloat16* bsrcH = bh + kbase + (size_t)bn * NTOT + bc * 8;
    const __nv_bfloat16* bsrcL = bl + kbase + (size_t)bn * NTOT + bc * 8;
    uint32_t bDstH = smb + BH_OFF + (uint32_t)(bn * BSTR + bc * 8) * 2;
    uint32_t bDstL = smb + BL_OFF + (uint32_t)(bn * BSTR + bc * 8) * 2;

    // ---- compute-side addressing ----
    const float* aBase = (const float*)(sm + A_OFF);
    int frow0 = wid * 16 + (lane >> 2);
    const float* aR0 = aBase + frow0 * ASTR + (lane & 3) * 2;
    const float* aR1 = aR0 + 8 * ASTR;
    uint32_t bLm = (uint32_t)((((lane & 7) + ((lane >> 4) << 3)) * BSTR + ((lane >> 3) & 1) * 8) * 2);

    float acc[8][4];
#pragma unroll
    for (int nb = 0; nb < 8; ++nb)
#pragma unroll
        for (int i = 0; i < 4; ++i) acc[nb][i] = 0.f;

    // ---- prologue: stages 0,1 ----
#pragma unroll
    for (int s = 0; s < 2; ++s) {
        uint32_t ad = aDst + s * ASTAGE;
        size_t ko = (size_t)s * KT;
#pragma unroll
        for (int j = 0; j < 4; ++j) cp16(ad + j * (32 * ASTR * 4), apj[j] + ko);
        cp16(bDstH + s * BSTAGE, bsrcH + ko);
        cp16(bDstL + s * BSTAGE, bsrcL + ko);
        CP_COMMIT();
    }

    for (int kt = 0; kt < NKT; ++kt) {
        int buf = kt % NSTAGE;
        CP_WAIT(1);
        __syncthreads();
        if (kt + 2 < NKT) {
            int s = (kt + 2) % NSTAGE;
            uint32_t ad = aDst + s * ASTAGE;
            size_t ko = (size_t)(kt + 2) * KT;
#pragma unroll
            for (int j = 0; j < 4; ++j) cp16(ad + j * (32 * ASTR * 4), apj[j] + ko);
            cp16(bDstH + s * BSTAGE, bsrcH + ko);
            cp16(bDstL + s * BSTAGE, bsrcL + ko);
        }
        CP_COMMIT();

        const float* a0 = aR0 + buf * (ASTAGE / 4);
        const float* a1 = aR1 + buf * (ASTAGE / 4);
        uint32_t bh_base = smb + BH_OFF + buf * BSTAGE + bLm;
        uint32_t bl_base = smb + BL_OFF + buf * BSTAGE + bLm;

#pragma unroll
        for (int ks = 0; ks < 2; ++ks) {
            int ko = ks * 16;
            float2 x0 = *(const float2*)(a0 + ko);
            float2 x1 = *(const float2*)(a1 + ko);
            float2 x2 = *(const float2*)(a0 + ko + 8);
            float2 x3 = *(const float2*)(a1 + ko + 8);
            uint32_t ahf[4], alf[4];
            split2(x0, ahf[0], alf[0]);
            split2(x1, ahf[1], alf[1]);
            split2(x2, ahf[2], alf[2]);
            split2(x3, ahf[3], alf[3]);

            uint32_t bhf[8][2], blf[8][2];
#pragma unroll
            for (int p = 0; p < 4; ++p) {
                uint32_t r[4];
                uint32_t o = (uint32_t)(p * 16 * BSTR * 2 + ks * 32);
                ldmx4(r, bh_base + o);
                bhf[p * 2][0] = r[0]; bhf[p * 2][1] = r[1];
                bhf[p * 2 + 1][0] = r[2]; bhf[p * 2 + 1][1] = r[3];
                ldmx4(r, bl_base + o);
                blf[p * 2][0] = r[0]; blf[p * 2][1] = r[1];
                blf[p * 2 + 1][0] = r[2]; blf[p * 2 + 1][1] = r[3];
            }
#pragma unroll
            for (int nb = 0; nb < 8; ++nb) {
                mma16816(acc[nb], ahf, bhf[nb]);
                mma16816(acc[nb], ahf, blf[nb]);
                mma16816(acc[nb], alf, bhf[nb]);
            }
        }
    }

    float* dst = g_part[split];
    int r0 = slotBase + wid * 16 + (lane >> 2);
#pragma unroll
    for (int nb = 0; nb < 8; ++nb) {
        int col = nb * 8 + (lane & 3) * 2;
        *(float2*)(dst + (size_t)r0 * D + col)       = make_float2(acc[nb][0], acc[nb][1]);
        *(float2*)(dst + (size_t)(r0 + 8) * D + col) = make_float2(acc[nb][2], acc[nb][3]);
    }
}

// -------- 5. gather + deterministic reduction + rank-1 user column for U rows --------
__global__ void k_gather(const float* __restrict__ adj,
                         const int* __restrict__ users, const int* __restrict__ pos,
                         const int* __restrict__ neg, float* __restrict__ out) {
    int t = blockIdx.x * 256 + threadIdx.x;
    int q = t >> 6, d = t & 63;
    int r;
    if (q < BATCH)          r = users[q];
    else if (q < 2 * BATCH) r = N_USER + pos[q - BATCH];
    else                    r = N_USER + neg[q - 2 * BATCH];
    int p = g_pos[r];
    size_t o = (size_t)p * D + d;
    float s = 0.f;
    if (p < UBASE) {
#pragma unroll
        for (int k = 0; k < NSPF; ++k) s += g_part[k][o];
    } else {
#pragma unroll
        for (int k = 0; k < NSPU; ++k) s += g_part[k][o];
        int u0 = users[0];
        s += adj[(size_t)r * NTOT + u0] * g_ego[(size_t)u0 * D + d];
    }
    out[t] = 0.25f * (g_ego[(size_t)r * D + d] + 3.0f * s);
}

extern "C" void kernel_launch(void* const* d_in, const int* in_sizes, int n_in,
                              void* d_out, int out_size) {
    const float* adj   = (const float*)d_in[0];
    const float* ue    = (const float*)d_in[1];
    const float* ie    = (const float*)d_in[2];
    const int*   users = (const int*)d_in[3];
    const int*   pos   = (const int*)d_in[4];
    const int*   neg   = (const int*)d_in[5];
    float*       out   = (float*)d_out;

    cudaFuncSetAttribute(k_main, cudaFuncAttributeMaxDynamicSharedMemorySize, SM_TOTAL);

    k_init<<<NTOT, D>>>(ue, ie);
    k_compact<<<1, 1024>>>(users, pos, neg);
    k_prepT<<<NTOT / 64, 256>>>();
    k_main<<<F_ITEMS + U_ITEMS, 256, SM_TOTAL>>>(adj);
    k_gather<<<(6 * BATCH * D) / 256, 256>>>(adj, users, pos, neg, out);
}

// round 10
// speedup vs baseline: 1.6210x; 1.0294x over previous
#include <cuda_runtime.h>
#include <cuda_bf16.h>
#include <cstdint>

#define N_USER   6144
#define NTOT     12288
#define D        64
#define BATCH    2048
#define NNEG     8192
#define MAXF     2049
#define MAXU     10240
#define UBASE    2176                 // 17 F-tiles * 128
#define SLOTS    (UBASE + MAXU)
#define KT       32                   // K per stage
#define NSPF     32                   // F splits: 384 K each
#define NSPU     16                   // U splits: 384 K each
#define KSPL     384
#define NKT      12
#define F_ITEMS  (17 * NSPF)          // 544
#define U_ITEMS  (80 * NSPU)          // 1280
#define NSTAGE   3
#define ASTR     40                   // fp32 units
#define BSTR     40                   // bf16 units

// ---- dynamic smem byte offsets ----
#define A_OFF    0
#define ASTAGE   20480                // 128*40*4
#define BH_OFF   (ASTAGE * NSTAGE)            // 61440
#define BSTAGE   5120                 // 64*40*2
#define BL_OFF   (BH_OFF + BSTAGE * NSTAGE)   // 76800
#define ROWP_OFF (BL_OFF + BSTAGE * NSTAGE)   // 92160
#define SM_TOTAL (ROWP_OFF + 128 * 8)         // 93184

// -------- device scratch --------
__device__ float g_ego[NTOT * D];
__device__ __nv_bfloat16 g_eThi[(size_t)D * NTOT], g_eTlo[(size_t)D * NTOT];
__device__ __nv_bfloat16 g_eMhi[(size_t)D * NTOT], g_eMlo[(size_t)D * NTOT];
__device__ int g_flag[NTOT], g_needed[NTOT];
__device__ int g_listF[MAXF], g_listU[MAXU], g_pos[NTOT];
__device__ int g_cF, g_cU;
__device__ float g_part[NSPF][(size_t)SLOTS * D];

__device__ __forceinline__ uint32_t smem_u32(const void* p) {
    uint32_t a;
    asm("{ .reg .u64 t; cvta.to.shared.u64 t, %1; cvt.u32.u64 %0, t; }" : "=r"(a) : "l"(p));
    return a;
}
__device__ __forceinline__ void cp16(uint32_t dst, const void* src) {
    asm volatile("cp.async.ca.shared.global [%0], [%1], 16;" :: "r"(dst), "l"(src));
}
#define CP_COMMIT() asm volatile("cp.async.commit_group;" ::: "memory")
#define CP_WAIT(n)  asm volatile("cp.async.wait_group %0;" :: "n"(n) : "memory")

__device__ __forceinline__ void ldmx4(uint32_t* r, uint32_t addr) {
    asm volatile("ldmatrix.sync.aligned.m8n8.x4.shared.b16 {%0,%1,%2,%3}, [%4];"
                 : "=r"(r[0]), "=r"(r[1]), "=r"(r[2]), "=r"(r[3]) : "r"(addr));
}
__device__ __forceinline__ void mma16816(float* c, const uint32_t* a, const uint32_t* b) {
    asm volatile("mma.sync.aligned.m16n8k16.row.col.f32.bf16.bf16.f32 "
                 "{%0,%1,%2,%3},{%4,%5,%6,%7},{%8,%9},{%0,%1,%2,%3};"
                 : "+f"(c[0]), "+f"(c[1]), "+f"(c[2]), "+f"(c[3])
                 : "r"(a[0]), "r"(a[1]), "r"(a[2]), "r"(a[3]), "r"(b[0]), "r"(b[1]));
}
__device__ __forceinline__ void split2(float2 x, uint32_t& h, uint32_t& l) {
    __nv_bfloat162 hb = __float22bfloat162_rn(x);
    float2 hf = __bfloat1622float2(hb);
    __nv_bfloat162 lb = __float22bfloat162_rn(make_float2(x.x - hf.x, x.y - hf.y));
    h = *(uint32_t*)&hb; l = *(uint32_t*)&lb;
}

// -------- 1. fused zero + scatter + deterministic compaction + slot map --------
__global__ void k_compact(const int* __restrict__ users, const int* __restrict__ pos,
                          const int* __restrict__ neg) {
    __shared__ int warpF[32], warpU[32];
    __shared__ int baseF, baseU;
    int tid = threadIdx.x, lane = tid & 31, wid = tid >> 5;
#pragma unroll
    for (int i = 0; i < NTOT / 1024; ++i) {
        g_flag[tid + i * 1024] = 0;
        g_needed[tid + i * 1024] = 0;
    }
    if (tid == 0) { baseF = 0; baseU = 0; }
    __syncthreads();
    if (tid == 0) g_flag[users[0]] = 1;
    for (int i = tid; i < NNEG; i += 1024) g_needed[N_USER + neg[i]] = 1;
    for (int i = tid; i < BATCH; i += 1024) {
        int rp = N_USER + pos[i];
        g_flag[rp] = 1; g_needed[rp] = 1;
        g_needed[users[i]] = 1;
    }
    __syncthreads();
    for (int base = 0; base < NTOT; base += 1024) {
        int i = base + tid;
        int f = g_flag[i];
        int u = (!f) && g_needed[i];
        unsigned bf = __ballot_sync(0xFFFFFFFFu, f);
        unsigned bu = __ballot_sync(0xFFFFFFFFu, u);
        if (lane == 0) { warpF[wid] = __popc(bf); warpU[wid] = __popc(bu); }
        __syncthreads();
        int offF = baseF, offU = baseU;
        for (int k = 0; k < wid; ++k) { offF += warpF[k]; offU += warpU[k]; }
        if (f) {
            int j = offF + __popc(bf & ((1u << lane) - 1u));
            g_listF[j] = i; g_pos[i] = j;
        }
        if (u) {
            int j = offU + __popc(bu & ((1u << lane) - 1u));
            g_listU[j] = i; g_pos[i] = UBASE + j;
        }
        __syncthreads();
        if (tid == 0)
            for (int k = 0; k < 32; ++k) { baseF += warpF[k]; baseU += warpU[k]; }
        __syncthreads();
    }
    if (tid == 0) { g_cF = baseF; g_cU = baseU; }
}

// -------- 2. fused init + transpose + bf16 hi/lo (+ masked upper half) --------
__global__ void k_pre(const float* __restrict__ ue, const float* __restrict__ ie) {
    __shared__ float tile[64][65];
    __shared__ int sflag[64];
    int k0 = blockIdx.x * 64;
    int tid = threadIdx.x;
    if (tid < 64) sflag[tid] = g_flag[k0 + tid];
    bool upper = (k0 >= N_USER);
    const float* src = upper ? (ie + (size_t)(k0 - N_USER) * D) : (ue + (size_t)k0 * D);
#pragma unroll
    for (int i = 0; i < 16; ++i) {
        int e = tid + i * 256;
        int k = e >> 6, n = e & 63;
        float x = src[(size_t)k * D + n];
        tile[k][n] = x;
        g_ego[(size_t)(k0 + k) * D + n] = x;
    }
    __syncthreads();
#pragma unroll
    for (int i = 0; i < 16; ++i) {
        int e = tid + i * 256;
        int n = e >> 6, kk = e & 63;
        float x = tile[kk][n];
        __nv_bfloat16 h = __float2bfloat16(x);
        float hf = __bfloat162float(h);
        __nv_bfloat16 l = __float2bfloat16(x - hf);
        size_t o = (size_t)n * NTOT + k0 + kk;
        g_eThi[o] = h; g_eTlo[o] = l;
        if (upper) {
            bool f = sflag[kk] != 0;
            __nv_bfloat16 z = __float2bfloat16(0.f);
            g_eMhi[o] = f ? h : z;
            g_eMlo[o] = f ? l : z;
        }
    }
}

// -------- 3. main GEMM: 32x32 warp tiles, 3-stage cp.async pipeline --------
__global__ void __launch_bounds__(256, 2) k_main(const float* __restrict__ adj) {
    extern __shared__ char sm[];
    uint32_t smb = smem_u32(sm);
    const float** sRow = (const float**)(sm + ROWP_OFF);

    int tid = threadIdx.x, wid = tid >> 5, lane = tid & 31;
    int cF = g_cF, cU = g_cU;
    int bx = blockIdx.x;

    int slotBase, j0, cnt, split;
    size_t kbase;
    const int* list;
    const __nv_bfloat16 *bh, *bl;
    if (bx < F_ITEMS) {
        int tile = bx >> 5; split = bx & (NSPF - 1);
        if (tile * 128 >= cF) return;
        j0 = tile * 128; slotBase = j0; list = g_listF; cnt = cF;
        bh = g_eThi; bl = g_eTlo;
        kbase = (size_t)split * KSPL;
    } else {
        int u = bx - F_ITEMS;
        int tile = u >> 4; split = u & (NSPU - 1);
        if (tile * 128 >= cU) return;
        j0 = tile * 128; slotBase = UBASE + j0; list = g_listU; cnt = cU;
        bh = g_eMhi; bl = g_eMlo;
        kbase = (size_t)N_USER + (size_t)split * KSPL;
    }

    if (tid < 128) {
        int j = j0 + tid; if (j >= cnt) j = cnt - 1;
        sRow[tid] = adj + (size_t)list[j] * NTOT + kbase;
    }
    __syncthreads();

    // ---- A staging map ----
    int r0s = tid >> 3, chs = tid & 7;
    const float* apj[4];
#pragma unroll
    for (int j = 0; j < 4; ++j) apj[j] = sRow[r0s + 32 * j] + chs * 4;
    uint32_t aDst = smb + A_OFF + (uint32_t)(r0s * ASTR + chs * 4) * 4;

    // ---- B staging map ----
    int bn = tid >> 2, bc = tid & 3;
    const __nv_bfloat16* bsrcH = bh + kbase + (size_t)bn * NTOT + bc * 8;
    const __nv_bfloat16* bsrcL = bl + kbase + (size_t)bn * NTOT + bc * 8;
    uint32_t bDstH = smb + BH_OFF + (uint32_t)(bn * BSTR + bc * 8) * 2;
    uint32_t bDstL = smb + BL_OFF + (uint32_t)(bn * BSTR + bc * 8) * 2;

    // ---- compute-side addressing: warp tile = 32 rows x 32 cols ----
    int mg = wid >> 1;                 // M group 0..3 -> rows mg*32
    int nh = wid & 1;                  // N half  0..1 -> cols nh*32
    const float* aBase = (const float*)(sm + A_OFF);
    int frow0 = mg * 32 + (lane >> 2);
    const float* aR0 = aBase + frow0 * ASTR + (lane & 3) * 2;   // rows +0
    const float* aR1 = aR0 + 8 * ASTR;                          // rows +8
    const float* aR2 = aR0 + 16 * ASTR;                         // rows +16
    const float* aR3 = aR0 + 24 * ASTR;                         // rows +24
    uint32_t bLm = (uint32_t)(((nh * 32 + (lane & 7) + ((lane >> 4) << 3)) * BSTR
                               + ((lane >> 3) & 1) * 8) * 2);

    float acc[2][4][4];                 // [mblock][nblock][frag]
#pragma unroll
    for (int mb = 0; mb < 2; ++mb)
#pragma unroll
        for (int nb = 0; nb < 4; ++nb)
#pragma unroll
            for (int i = 0; i < 4; ++i) acc[mb][nb][i] = 0.f;

    // ---- prologue: stages 0,1 ----
#pragma unroll
    for (int s = 0; s < 2; ++s) {
        uint32_t ad = aDst + s * ASTAGE;
        size_t ko = (size_t)s * KT;
#pragma unroll
        for (int j = 0; j < 4; ++j) cp16(ad + j * (32 * ASTR * 4), apj[j] + ko);
        cp16(bDstH + s * BSTAGE, bsrcH + ko);
        cp16(bDstL + s * BSTAGE, bsrcL + ko);
        CP_COMMIT();
    }

    for (int kt = 0; kt < NKT; ++kt) {
        int buf = kt % NSTAGE;
        CP_WAIT(1);
        __syncthreads();
        if (kt + 2 < NKT) {
            int s = (kt + 2) % NSTAGE;
            uint32_t ad = aDst + s * ASTAGE;
            size_t ko = (size_t)(kt + 2) * KT;
#pragma unroll
            for (int j = 0; j < 4; ++j) cp16(ad + j * (32 * ASTR * 4), apj[j] + ko);
            cp16(bDstH + s * BSTAGE, bsrcH + ko);
            cp16(bDstL + s * BSTAGE, bsrcL + ko);
        }
        CP_COMMIT();

        int abufo = buf * (ASTAGE / 4);
        uint32_t bh_base = smb + BH_OFF + buf * BSTAGE + bLm;
        uint32_t bl_base = smb + BL_OFF + buf * BSTAGE + bLm;

#pragma unroll
        for (int ks = 0; ks < 2; ++ks) {
            int ko = ks * 16;
            // A fragments: two 16-row blocks
            uint32_t ahf[2][4], alf[2][4];
            {
                float2 x0 = *(const float2*)(aR0 + abufo + ko);
                float2 x1 = *(const float2*)(aR1 + abufo + ko);
                float2 x2 = *(const float2*)(aR0 + abufo + ko + 8);
                float2 x3 = *(const float2*)(aR1 + abufo + ko + 8);
                split2(x0, ahf[0][0], alf[0][0]);
                split2(x1, ahf[0][1], alf[0][1]);
                split2(x2, ahf[0][2], alf[0][2]);
                split2(x3, ahf[0][3], alf[0][3]);
                x0 = *(const float2*)(aR2 + abufo + ko);
                x1 = *(const float2*)(aR3 + abufo + ko);
                x2 = *(const float2*)(aR2 + abufo + ko + 8);
                x3 = *(const float2*)(aR3 + abufo + ko + 8);
                split2(x0, ahf[1][0], alf[1][0]);
                split2(x1, ahf[1][1], alf[1][1]);
                split2(x2, ahf[1][2], alf[1][2]);
                split2(x3, ahf[1][3], alf[1][3]);
            }
            // B fragments: 4 n-blocks (32 cols) via 2 hi + 2 lo ldmx4
            uint32_t bhf[4][2], blf[4][2];
            {
                uint32_t r[4];
                ldmx4(r, bh_base + ks * 32);
                bhf[0][0] = r[0]; bhf[0][1] = r[1]; bhf[1][0] = r[2]; bhf[1][1] = r[3];
                ldmx4(r, bh_base + 16 * BSTR * 2 + ks * 32);
                bhf[2][0] = r[0]; bhf[2][1] = r[1]; bhf[3][0] = r[2]; bhf[3][1] = r[3];
                ldmx4(r, bl_base + ks * 32);
                blf[0][0] = r[0]; blf[0][1] = r[1]; blf[1][0] = r[2]; blf[1][1] = r[3];
                ldmx4(r, bl_base + 16 * BSTR * 2 + ks * 32);
                blf[2][0] = r[0]; blf[2][1] = r[1]; blf[3][0] = r[2]; blf[3][1] = r[3];
            }
#pragma unroll
            for (int mb = 0; mb < 2; ++mb)
#pragma unroll
                for (int nb = 0; nb < 4; ++nb) {
                    mma16816(acc[mb][nb], ahf[mb], bhf[nb]);
                    mma16816(acc[mb][nb], ahf[mb], blf[nb]);
                    mma16816(acc[mb][nb], alf[mb], bhf[nb]);
                }
        }
    }

    float* dst = g_part[split];
#pragma unroll
    for (int mb = 0; mb < 2; ++mb) {
        int r0 = slotBase + mg * 32 + mb * 16 + (lane >> 2);
#pragma unroll
        for (int nb = 0; nb < 4; ++nb) {
            int col = nh * 32 + nb * 8 + (lane & 3) * 2;
            *(float2*)(dst + (size_t)r0 * D + col)       = make_float2(acc[mb][nb][0], acc[mb][nb][1]);
            *(float2*)(dst + (size_t)(r0 + 8) * D + col) = make_float2(acc[mb][nb][2], acc[mb][nb][3]);
        }
    }
}

// -------- 4. gather + deterministic reduction + rank-1 user column for U rows --------
__global__ void k_gather(const float* __restrict__ adj,
                         const int* __restrict__ users, const int* __restrict__ pos,
                         const int* __restrict__ neg, float* __restrict__ out) {
    int t = blockIdx.x * 256 + threadIdx.x;
    int q = t >> 6, d = t & 63;
    int r;
    if (q < BATCH)          r = users[q];
    else if (q < 2 * BATCH) r = N_USER + pos[q - BATCH];
    else                    r = N_USER + neg[q - 2 * BATCH];
    int p = g_pos[r];
    size_t o = (size_t)p * D + d;
    float s = 0.f;
    if (p < UBASE) {
#pragma unroll
        for (int k = 0; k < NSPF; ++k) s += g_part[k][o];
    } else {
#pragma unroll
        for (int k = 0; k < NSPU; ++k) s += g_part[k][o];
        int u0 = users[0];
        s += adj[(size_t)r * NTOT + u0] * g_ego[(size_t)u0 * D + d];
    }
    out[t] = 0.25f * (g_ego[(size_t)r * D + d] + 3.0f * s);
}

extern "C" void kernel_launch(void* const* d_in, const int* in_sizes, int n_in,
                              void* d_out, int out_size) {
    const float* adj   = (const float*)d_in[0];
    const float* ue    = (const float*)d_in[1];
    const float* ie    = (const float*)d_in[2];
    const int*   users = (const int*)d_in[3];
    const int*   pos   = (const int*)d_in[4];
    const int*   neg   = (const int*)d_in[5];
    float*       out   = (float*)d_out;

    cudaFuncSetAttribute(k_main, cudaFuncAttributeMaxDynamicSharedMemorySize, SM_TOTAL);

    k_compact<<<1, 1024>>>(users, pos, neg);
    k_pre<<<NTOT / 64, 256>>>(ue, ie);
    k_main<<<F_ITEMS + U_ITEMS, 256, SM_TOTAL>>>(adj);
    k_gather<<<(6 * BATCH * D) / 256, 256>>>(adj, users, pos, neg, out);
}

// round 11
// speedup vs baseline: 1.8297x; 1.1288x over previous
#include <cuda_runtime.h>
#include <cuda_bf16.h>
#include <cstdint>

#define N_USER   6144
#define NTOT     12288
#define D        64
#define BATCH    2048
#define NNEG     8192
#define MAXF     2049
#define MAXU     10240
#define UBASE    2176                 // 17 F-tiles * 128
#define SLOTS    (UBASE + MAXU)
#define KT       32                   // K per stage
#define NSPF     16                   // F splits: 768 K each
#define NSPU     8                    // U splits: 768 K each
#define KSPL     768
#define NKT      24
#define F_ITEMS  (17 * NSPF)          // 272
#define U_ITEMS  (80 * NSPU)          // 640
#define NSTAGE   3
#define ASTR     40                   // fp32 units
#define BSTR     40                   // bf16 units

// ---- dynamic smem byte offsets (k_main) ----
#define A_OFF    0
#define ASTAGE   20480                // 128*40*4
#define BH_OFF   (ASTAGE * NSTAGE)            // 61440
#define BSTAGE   5120                 // 64*40*2
#define BL_OFF   (BH_OFF + BSTAGE * NSTAGE)   // 76800
#define ROWP_OFF (BL_OFF + BSTAGE * NSTAGE)   // 92160
#define SM_TOTAL (ROWP_OFF + 128 * 8)         // 93184

// -------- device scratch --------
__device__ float g_ego[NTOT * D];
__device__ __nv_bfloat16 g_eThi[(size_t)D * NTOT], g_eTlo[(size_t)D * NTOT];
__device__ __nv_bfloat16 g_eMhi[(size_t)D * NTOT], g_eMlo[(size_t)D * NTOT];
__device__ int g_flag[NTOT];
__device__ int g_listF[MAXF], g_listU[MAXU], g_pos[NTOT];
__device__ int g_cF, g_cU;
__device__ float g_part[NSPF][(size_t)SLOTS * D];

__device__ __forceinline__ uint32_t smem_u32(const void* p) {
    uint32_t a;
    asm("{ .reg .u64 t; cvta.to.shared.u64 t, %1; cvt.u32.u64 %0, t; }" : "=r"(a) : "l"(p));
    return a;
}
__device__ __forceinline__ void cp16(uint32_t dst, const void* src) {
    asm volatile("cp.async.ca.shared.global [%0], [%1], 16;" :: "r"(dst), "l"(src));
}
#define CP_COMMIT() asm volatile("cp.async.commit_group;" ::: "memory")
#define CP_WAIT(n)  asm volatile("cp.async.wait_group %0;" :: "n"(n) : "memory")

__device__ __forceinline__ void ldmx4(uint32_t* r, uint32_t addr) {
    asm volatile("ldmatrix.sync.aligned.m8n8.x4.shared.b16 {%0,%1,%2,%3}, [%4];"
                 : "=r"(r[0]), "=r"(r[1]), "=r"(r[2]), "=r"(r[3]) : "r"(addr));
}
__device__ __forceinline__ void mma16816(float* c, const uint32_t* a, const uint32_t* b) {
    asm volatile("mma.sync.aligned.m16n8k16.row.col.f32.bf16.bf16.f32 "
                 "{%0,%1,%2,%3},{%4,%5,%6,%7},{%8,%9},{%0,%1,%2,%3};"
                 : "+f"(c[0]), "+f"(c[1]), "+f"(c[2]), "+f"(c[3])
                 : "r"(a[0]), "r"(a[1]), "r"(a[2]), "r"(a[3]), "r"(b[0]), "r"(b[1]));
}
__device__ __forceinline__ void split2(float2 x, uint32_t& h, uint32_t& l) {
    __nv_bfloat162 hb = __float22bfloat162_rn(x);
    float2 hf = __bfloat1622float2(hb);
    __nv_bfloat162 lb = __float22bfloat162_rn(make_float2(x.x - hf.x, x.y - hf.y));
    h = *(uint32_t*)&hb; l = *(uint32_t*)&lb;
}

// -------- 1. fused scatter + compaction via SMEM byte maps (1 block) --------
__global__ void k_compact(const int* __restrict__ users, const int* __restrict__ pos,
                          const int* __restrict__ neg) {
    __shared__ unsigned char sflag[NTOT], sneed[NTOT];
    __shared__ int warpF[32], warpU[32];
    __shared__ int baseF, baseU;
    int tid = threadIdx.x, lane = tid & 31, wid = tid >> 5;
#pragma unroll
    for (int i = 0; i < NTOT / 4096; ++i) {
        ((uint32_t*)sflag)[tid + i * 1024] = 0;
        ((uint32_t*)sneed)[tid + i * 1024] = 0;
    }
    if (tid == 0) { baseF = 0; baseU = 0; }
    __syncthreads();
    if (tid == 0) sflag[users[0]] = 1;
    for (int i = tid; i < NNEG; i += 1024) sneed[N_USER + neg[i]] = 1;
    for (int i = tid; i < BATCH; i += 1024) {
        int rp = N_USER + pos[i];
        sflag[rp] = 1; sneed[rp] = 1;
        sneed[users[i]] = 1;
    }
    __syncthreads();
    for (int base = 0; base < NTOT; base += 1024) {
        int i = base + tid;
        int f = sflag[i];
        int u = (!f) && sneed[i];
        g_flag[i] = f;
        unsigned bf = __ballot_sync(0xFFFFFFFFu, f);
        unsigned bu = __ballot_sync(0xFFFFFFFFu, u);
        if (lane == 0) { warpF[wid] = __popc(bf); warpU[wid] = __popc(bu); }
        __syncthreads();
        int offF = baseF, offU = baseU;
        for (int k = 0; k < wid; ++k) { offF += warpF[k]; offU += warpU[k]; }
        if (f) {
            int j = offF + __popc(bf & ((1u << lane) - 1u));
            g_listF[j] = i; g_pos[i] = j;
        }
        if (u) {
            int j = offU + __popc(bu & ((1u << lane) - 1u));
            g_listU[j] = i; g_pos[i] = UBASE + j;
        }
        __syncthreads();
        if (tid == 0)
            for (int k = 0; k < 32; ++k) { baseF += warpF[k]; baseU += warpU[k]; }
        __syncthreads();
    }
    if (tid == 0) { g_cF = baseF; g_cU = baseU; }
}

// -------- 2. fused init + transpose + bf16 hi/lo (+ masked upper half) --------
__global__ void k_pre(const float* __restrict__ ue, const float* __restrict__ ie) {
    __shared__ float tile[64][65];
    __shared__ int sflag[64];
    int k0 = blockIdx.x * 64;
    int tid = threadIdx.x;
    if (tid < 64) sflag[tid] = g_flag[k0 + tid];
    bool upper = (k0 >= N_USER);
    const float* src = upper ? (ie + (size_t)(k0 - N_USER) * D) : (ue + (size_t)k0 * D);
#pragma unroll
    for (int i = 0; i < 16; ++i) {
        int e = tid + i * 256;
        int k = e >> 6, n = e & 63;
        float x = src[(size_t)k * D + n];
        tile[k][n] = x;
        g_ego[(size_t)(k0 + k) * D + n] = x;
    }
    __syncthreads();
#pragma unroll
    for (int i = 0; i < 16; ++i) {
        int e = tid + i * 256;
        int n = e >> 6, kk = e & 63;
        float x = tile[kk][n];
        __nv_bfloat16 h = __float2bfloat16(x);
        float hf = __bfloat162float(h);
        __nv_bfloat16 l = __float2bfloat16(x - hf);
        size_t o = (size_t)n * NTOT + k0 + kk;
        g_eThi[o] = h; g_eTlo[o] = l;
        if (upper) {
            bool f = sflag[kk] != 0;
            __nv_bfloat16 z = __float2bfloat16(0.f);
            g_eMhi[o] = f ? h : z;
            g_eMlo[o] = f ? l : z;
        }
    }
}

// -------- 3. main GEMM: 32x32 warp tiles, 3-stage cp.async pipeline --------
__global__ void __launch_bounds__(256, 2) k_main(const float* __restrict__ adj) {
    extern __shared__ char sm[];
    uint32_t smb = smem_u32(sm);
    const float** sRow = (const float**)(sm + ROWP_OFF);

    int tid = threadIdx.x, wid = tid >> 5, lane = tid & 31;
    int cF = g_cF, cU = g_cU;
    int bx = blockIdx.x;

    int slotBase, j0, cnt, split;
    size_t kbase;
    const int* list;
    const __nv_bfloat16 *bh, *bl;
    if (bx < F_ITEMS) {
        int tile = bx >> 4; split = bx & (NSPF - 1);
        if (tile * 128 >= cF) return;
        j0 = tile * 128; slotBase = j0; list = g_listF; cnt = cF;
        bh = g_eThi; bl = g_eTlo;
        kbase = (size_t)split * KSPL;
    } else {
        int u = bx - F_ITEMS;
        int tile = u >> 3; split = u & (NSPU - 1);
        if (tile * 128 >= cU) return;
        j0 = tile * 128; slotBase = UBASE + j0; list = g_listU; cnt = cU;
        bh = g_eMhi; bl = g_eMlo;
        kbase = (size_t)N_USER + (size_t)split * KSPL;
    }

    if (tid < 128) {
        int j = j0 + tid; if (j >= cnt) j = cnt - 1;
        sRow[tid] = adj + (size_t)list[j] * NTOT + kbase;
    }
    __syncthreads();

    // ---- A staging map ----
    int r0s = tid >> 3, chs = tid & 7;
    const float* apj[4];
#pragma unroll
    for (int j = 0; j < 4; ++j) apj[j] = sRow[r0s + 32 * j] + chs * 4;
    uint32_t aDst = smb + A_OFF + (uint32_t)(r0s * ASTR + chs * 4) * 4;

    // ---- B staging map ----
    int bn = tid >> 2, bc = tid & 3;
    const __nv_bfloat16* bsrcH = bh + kbase + (size_t)bn * NTOT + bc * 8;
    const __nv_bfloat16* bsrcL = bl + kbase + (size_t)bn * NTOT + bc * 8;
    uint32_t bDstH = smb + BH_OFF + (uint32_t)(bn * BSTR + bc * 8) * 2;
    uint32_t bDstL = smb + BL_OFF + (uint32_t)(bn * BSTR + bc * 8) * 2;

    // ---- compute-side addressing: warp tile = 32 rows x 32 cols ----
    int mg = wid >> 1;
    int nh = wid & 1;
    const float* aBase = (const float*)(sm + A_OFF);
    int frow0 = mg * 32 + (lane >> 2);
    const float* aR0 = aBase + frow0 * ASTR + (lane & 3) * 2;
    const float* aR1 = aR0 + 8 * ASTR;
    const float* aR2 = aR0 + 16 * ASTR;
    const float* aR3 = aR0 + 24 * ASTR;
    uint32_t bLm = (uint32_t)(((nh * 32 + (lane & 7) + ((lane >> 4) << 3)) * BSTR
                               + ((lane >> 3) & 1) * 8) * 2);

    float acc[2][4][4];
#pragma unroll
    for (int mb = 0; mb < 2; ++mb)
#pragma unroll
        for (int nb = 0; nb < 4; ++nb)
#pragma unroll
            for (int i = 0; i < 4; ++i) acc[mb][nb][i] = 0.f;

    // ---- prologue: stages 0,1 ----
#pragma unroll
    for (int s = 0; s < 2; ++s) {
        uint32_t ad = aDst + s * ASTAGE;
        size_t ko = (size_t)s * KT;
#pragma unroll
        for (int j = 0; j < 4; ++j) cp16(ad + j * (32 * ASTR * 4), apj[j] + ko);
        cp16(bDstH + s * BSTAGE, bsrcH + ko);
        cp16(bDstL + s * BSTAGE, bsrcL + ko);
        CP_COMMIT();
    }

    for (int kt = 0; kt < NKT; ++kt) {
        int buf = kt % NSTAGE;
        CP_WAIT(1);
        __syncthreads();
        if (kt + 2 < NKT) {
            int s = (kt + 2) % NSTAGE;
            uint32_t ad = aDst + s * ASTAGE;
            size_t ko = (size_t)(kt + 2) * KT;
#pragma unroll
            for (int j = 0; j < 4; ++j) cp16(ad + j * (32 * ASTR * 4), apj[j] + ko);
            cp16(bDstH + s * BSTAGE, bsrcH + ko);
            cp16(bDstL + s * BSTAGE, bsrcL + ko);
        }
        CP_COMMIT();

        int abufo = buf * (ASTAGE / 4);
        uint32_t bh_base = smb + BH_OFF + buf * BSTAGE + bLm;
        uint32_t bl_base = smb + BL_OFF + buf * BSTAGE + bLm;

#pragma unroll
        for (int ks = 0; ks < 2; ++ks) {
            int ko = ks * 16;
            uint32_t ahf[2][4], alf[2][4];
            {
                float2 x0 = *(const float2*)(aR0 + abufo + ko);
                float2 x1 = *(const float2*)(aR1 + abufo + ko);
                float2 x2 = *(const float2*)(aR0 + abufo + ko + 8);
                float2 x3 = *(const float2*)(aR1 + abufo + ko + 8);
                split2(x0, ahf[0][0], alf[0][0]);
                split2(x1, ahf[0][1], alf[0][1]);
                split2(x2, ahf[0][2], alf[0][2]);
                split2(x3, ahf[0][3], alf[0][3]);
                x0 = *(const float2*)(aR2 + abufo + ko);
                x1 = *(const float2*)(aR3 + abufo + ko);
                x2 = *(const float2*)(aR2 + abufo + ko + 8);
                x3 = *(const float2*)(aR3 + abufo + ko + 8);
                split2(x0, ahf[1][0], alf[1][0]);
                split2(x1, ahf[1][1], alf[1][1]);
                split2(x2, ahf[1][2], alf[1][2]);
                split2(x3, ahf[1][3], alf[1][3]);
            }
            uint32_t bhf[4][2], blf[4][2];
            {
                uint32_t r[4];
                ldmx4(r, bh_base + ks * 32);
                bhf[0][0] = r[0]; bhf[0][1] = r[1]; bhf[1][0] = r[2]; bhf[1][1] = r[3];
                ldmx4(r, bh_base + 16 * BSTR * 2 + ks * 32);
                bhf[2][0] = r[0]; bhf[2][1] = r[1]; bhf[3][0] = r[2]; bhf[3][1] = r[3];
                ldmx4(r, bl_base + ks * 32);
                blf[0][0] = r[0]; blf[0][1] = r[1]; blf[1][0] = r[2]; blf[1][1] = r[3];
                ldmx4(r, bl_base + 16 * BSTR * 2 + ks * 32);
                blf[2][0] = r[0]; blf[2][1] = r[1]; blf[3][0] = r[2]; blf[3][1] = r[3];
            }
#pragma unroll
            for (int mb = 0; mb < 2; ++mb)
#pragma unroll
                for (int nb = 0; nb < 4; ++nb) {
                    mma16816(acc[mb][nb], ahf[mb], bhf[nb]);
                    mma16816(acc[mb][nb], ahf[mb], blf[nb]);
                    mma16816(acc[mb][nb], alf[mb], bhf[nb]);
                }
        }
    }

    float* dst = g_part[split];
#pragma unroll
    for (int mb = 0; mb < 2; ++mb) {
        int r0 = slotBase + mg * 32 + mb * 16 + (lane >> 2);
#pragma unroll
        for (int nb = 0; nb < 4; ++nb) {
            int col = nh * 32 + nb * 8 + (lane & 3) * 2;
            *(float2*)(dst + (size_t)r0 * D + col)       = make_float2(acc[mb][nb][0], acc[mb][nb][1]);
            *(float2*)(dst + (size_t)(r0 + 8) * D + col) = make_float2(acc[mb][nb][2], acc[mb][nb][3]);
        }
    }
}

// -------- 4. gather + deterministic reduction + rank-1 user column for U rows --------
__global__ void k_gather(const float* __restrict__ adj,
                         const int* __restrict__ users, const int* __restrict__ pos,
                         const int* __restrict__ neg, float* __restrict__ out) {
    int t = blockIdx.x * 256 + threadIdx.x;
    int q = t >> 6, d = t & 63;
    int r;
    if (q < BATCH)          r = users[q];
    else if (q < 2 * BATCH) r = N_USER + pos[q - BATCH];
    else                    r = N_USER + neg[q - 2 * BATCH];
    int p = g_pos[r];
    size_t o = (size_t)p * D + d;
    float s = 0.f;
    if (p < UBASE) {
#pragma unroll
        for (int k = 0; k < NSPF; ++k) s += g_part[k][o];
    } else {
#pragma unroll
        for (int k = 0; k < NSPU; ++k) s += g_part[k][o];
        int u0 = users[0];
        s += adj[(size_t)r * NTOT + u0] * g_ego[(size_t)u0 * D + d];
    }
    out[t] = 0.25f * (g_ego[(size_t)r * D + d] + 3.0f * s);
}

extern "C" void kernel_launch(void* const* d_in, const int* in_sizes, int n_in,
                              void* d_out, int out_size) {
    const float* adj   = (const float*)d_in[0];
    const float* ue    = (const float*)d_in[1];
    const float* ie    = (const float*)d_in[2];
    const int*   users = (const int*)d_in[3];
    const int*   pos   = (const int*)d_in[4];
    const int*   neg   = (const int*)d_in[5];
    float*       out   = (float*)d_out;

    cudaFuncSetAttribute(k_main, cudaFuncAttributeMaxDynamicSharedMemorySize, SM_TOTAL);

    k_compact<<<1, 1024>>>(users, pos, neg);
    k_pre<<<NTOT / 64, 256>>>(ue, ie);
    k_main<<<F_ITEMS + U_ITEMS, 256, SM_TOTAL>>>(adj);
    k_gather<<<(6 * BATCH * D) / 256, 256>>>(adj, users, pos, neg, out);
}

// round 14
// speedup vs baseline: 1.9834x; 1.0840x over previous
#include <cuda_runtime.h>
#include <cuda_bf16.h>
#include <cstdint>

#define N_USER   6144
#define NTOT     12288
#define D        64
#define BATCH    2048
#define NNEG     8192
#define MAXF     2049
#define MAXU     10240
#define UBASE    2176                 // 17 F-tiles * 128
#define SLOTS    (UBASE + MAXU)
#define KT       32                   // K per stage
#define NSPF     16                   // F splits: 768 K each
#define NSPU     8                    // U splits: 768 K each
#define KSPL     768
#define NKT      24
#define F_ITEMS  (17 * NSPF)          // 272
#define U_ITEMS  (80 * NSPU)          // 640
#define NSTAGE   3
#define ASTR     40                   // fp32 units
#define BSTR     40                   // bf16 units

// ---- dynamic smem byte offsets (k_main) ----
#define A_OFF    0
#define ASTAGE   20480                // 128*40*4
#define BH_OFF   (ASTAGE * NSTAGE)            // 61440
#define BSTAGE   5120                 // 64*40*2
#define BL_OFF   (BH_OFF + BSTAGE * NSTAGE)   // 76800
#define ROWP_OFF (BL_OFF + BSTAGE * NSTAGE)   // 92160
#define SM_TOTAL (ROWP_OFF + 128 * 8)         // 93184

// -------- device scratch (16B-aligned: accessed via float4/uint2) --------
__device__ __align__(16) float g_ego[NTOT * D];
__device__ __align__(16) __nv_bfloat16 g_eThi[(size_t)D * NTOT];
__device__ __align__(16) __nv_bfloat16 g_eTlo[(size_t)D * NTOT];
__device__ __align__(16) __nv_bfloat16 g_eMhi[(size_t)D * NTOT];
__device__ __align__(16) __nv_bfloat16 g_eMlo[(size_t)D * NTOT];
__device__ int g_flag[NTOT];
__device__ int g_listF[MAXF], g_listU[MAXU], g_pos[NTOT];
__device__ int g_cF, g_cU;
__device__ __align__(16) float g_part[NSPF][(size_t)SLOTS * D];

__device__ __forceinline__ uint32_t smem_u32(const void* p) {
    uint32_t a;
    asm("{ .reg .u64 t; cvta.to.shared.u64 t, %1; cvt.u32.u64 %0, t; }" : "=r"(a) : "l"(p));
    return a;
}
// L1-bypassing async copy: streaming data, no L1 allocation
__device__ __forceinline__ void cp16cg(uint32_t dst, const void* src) {
    asm volatile("cp.async.cg.shared.global [%0], [%1], 16;" :: "r"(dst), "l"(src));
}
#define CP_COMMIT() asm volatile("cp.async.commit_group;" ::: "memory")
#define CP_WAIT(n)  asm volatile("cp.async.wait_group %0;" :: "n"(n) : "memory")

__device__ __forceinline__ void ldmx4(uint32_t* r, uint32_t addr) {
    asm volatile("ldmatrix.sync.aligned.m8n8.x4.shared.b16 {%0,%1,%2,%3}, [%4];"
                 : "=r"(r[0]), "=r"(r[1]), "=r"(r[2]), "=r"(r[3]) : "r"(addr));
}
__device__ __forceinline__ void mma16816(float* c, const uint32_t* a, const uint32_t* b) {
    asm volatile("mma.sync.aligned.m16n8k16.row.col.f32.bf16.bf16.f32 "
                 "{%0,%1,%2,%3},{%4,%5,%6,%7},{%8,%9},{%0,%1,%2,%3};"
                 : "+f"(c[0]), "+f"(c[1]), "+f"(c[2]), "+f"(c[3])
                 : "r"(a[0]), "r"(a[1]), "r"(a[2]), "r"(a[3]), "r"(b[0]), "r"(b[1]));
}
__device__ __forceinline__ void split2(float2 x, uint32_t& h, uint32_t& l) {
    __nv_bfloat162 hb = __float22bfloat162_rn(x);
    float2 hf = __bfloat1622float2(hb);
    __nv_bfloat162 lb = __float22bfloat162_rn(make_float2(x.x - hf.x, x.y - hf.y));
    h = *(uint32_t*)&hb; l = *(uint32_t*)&lb;
}

// -------- 1. fused scatter + compaction via SMEM byte maps (1 block) --------
__global__ void k_compact(const int* __restrict__ users, const int* __restrict__ pos,
                          const int* __restrict__ neg) {
    __shared__ unsigned char sflag[NTOT], sneed[NTOT];
    __shared__ int warpF[32], warpU[32];
    __shared__ int baseF, baseU;
    int tid = threadIdx.x, lane = tid & 31, wid = tid >> 5;
#pragma unroll
    for (int i = 0; i < NTOT / 4096; ++i) {
        ((uint32_t*)sflag)[tid + i * 1024] = 0;
        ((uint32_t*)sneed)[tid + i * 1024] = 0;
    }
    if (tid == 0) { baseF = 0; baseU = 0; }
    __syncthreads();
    if (tid == 0) sflag[users[0]] = 1;
    for (int i = tid; i < NNEG; i += 1024) sneed[N_USER + neg[i]] = 1;
    for (int i = tid; i < BATCH; i += 1024) {
        int rp = N_USER + pos[i];
        sflag[rp] = 1; sneed[rp] = 1;
        sneed[users[i]] = 1;
    }
    __syncthreads();
    for (int base = 0; base < NTOT; base += 1024) {
        int i = base + tid;
        int f = sflag[i];
        int u = (!f) && sneed[i];
        g_flag[i] = f;
        unsigned bf = __ballot_sync(0xFFFFFFFFu, f);
        unsigned bu = __ballot_sync(0xFFFFFFFFu, u);
        if (lane == 0) { warpF[wid] = __popc(bf); warpU[wid] = __popc(bu); }
        __syncthreads();
        int offF = baseF, offU = baseU;
        for (int k = 0; k < wid; ++k) { offF += warpF[k]; offU += warpU[k]; }
        if (f) {
            int j = offF + __popc(bf & ((1u << lane) - 1u));
            g_listF[j] = i; g_pos[i] = j;
        }
        if (u) {
            int j = offU + __popc(bu & ((1u << lane) - 1u));
            g_listU[j] = i; g_pos[i] = UBASE + j;
        }
        __syncthreads();
        if (tid == 0)
            for (int k = 0; k < 32; ++k) { baseF += warpF[k]; baseU += warpU[k]; }
        __syncthreads();
    }
    if (tid == 0) { g_cF = baseF; g_cU = baseU; }
}

// -------- 2. fused init + transpose + bf16 hi/lo --------
// float4 global loads/stores; SCALAR smem tile stores (65-pad rows are not
// 16B-aligned -> vector STS would trap); uint2 packed global bf16 stores.
__global__ void k_pre(const float* __restrict__ ue, const float* __restrict__ ie) {
    __shared__ float tile[64][65];
    __shared__ int sflag[64];
    int k0 = blockIdx.x * 64;
    int tid = threadIdx.x;
    if (tid < 64) sflag[tid] = g_flag[k0 + tid];
    bool upper = (k0 >= N_USER);
    const float* src = upper ? (ie + (size_t)(k0 - N_USER) * D) : (ue + (size_t)k0 * D);
#pragma unroll
    for (int i = 0; i < 4; ++i) {
        int e = tid + i * 256;            // 1024 float4 chunks
        int k = e >> 4, ng = e & 15;
        float4 v = *(const float4*)(src + (size_t)k * D + ng * 4);
        tile[k][ng * 4 + 0] = v.x;
        tile[k][ng * 4 + 1] = v.y;
        tile[k][ng * 4 + 2] = v.z;
        tile[k][ng * 4 + 3] = v.w;
        *(float4*)(g_ego + (size_t)(k0 + k) * D + ng * 4) = v;
    }
    __syncthreads();
    __nv_bfloat16 z = __float2bfloat16(0.f);
#pragma unroll
    for (int i = 0; i < 4; ++i) {
        int e = tid + i * 256;            // 1024 groups (64 n x 16 kg)
        int n = e >> 4, kg = e & 15;
        int k = kg * 4;
        uint32_t vh[2], vl[2], vmh[2], vml[2];
#pragma unroll
        for (int j = 0; j < 2; ++j) {
            float x0 = tile[k + 2 * j][n];
            float x1 = tile[k + 2 * j + 1][n];
            __nv_bfloat16 h0 = __float2bfloat16(x0), h1 = __float2bfloat16(x1);
            __nv_bfloat16 l0 = __float2bfloat16(x0 - __bfloat162float(h0));
            __nv_bfloat16 l1 = __float2bfloat16(x1 - __bfloat162float(h1));
            __nv_bfloat162 hp = __halves2bfloat162(h0, h1);
            __nv_bfloat162 lp = __halves2bfloat162(l0, l1);
            vh[j] = *(uint32_t*)&hp; vl[j] = *(uint32_t*)&lp;
            bool f0 = sflag[k + 2 * j] != 0, f1 = sflag[k + 2 * j + 1] != 0;
            __nv_bfloat162 mhp = __halves2bfloat162(f0 ? h0 : z, f1 ? h1 : z);
            __nv_bfloat162 mlp = __halves2bfloat162(f0 ? l0 : z, f1 ? l1 : z);
            vmh[j] = *(uint32_t*)&mhp; vml[j] = *(uint32_t*)&mlp;
        }
        size_t o = (size_t)n * NTOT + k0 + k;   // multiple of 4 elems = 8B
        *(uint2*)(g_eThi + o) = make_uint2(vh[0], vh[1]);
        *(uint2*)(g_eTlo + o) = make_uint2(vl[0], vl[1]);
        if (upper) {
            *(uint2*)(g_eMhi + o) = make_uint2(vmh[0], vmh[1]);
            *(uint2*)(g_eMlo + o) = make_uint2(vml[0], vml[1]);
        }
    }
}

// -------- 3. main GEMM: 32x32 warp tiles, 3-stage cp.async.cg pipeline --------
__global__ void __launch_bounds__(256, 2) k_main(const float* __restrict__ adj) {
    extern __shared__ char sm[];
    uint32_t smb = smem_u32(sm);
    const float** sRow = (const float**)(sm + ROWP_OFF);

    int tid = threadIdx.x, wid = tid >> 5, lane = tid & 31;
    int cF = g_cF, cU = g_cU;
    int bx = blockIdx.x;

    int slotBase, j0, cnt, split;
    size_t kbase;
    const int* list;
    const __nv_bfloat16 *bh, *bl;
    if (bx < F_ITEMS) {
        int tile = bx >> 4; split = bx & (NSPF - 1);
        if (tile * 128 >= cF) return;
        j0 = tile * 128; slotBase = j0; list = g_listF; cnt = cF;
        bh = g_eThi; bl = g_eTlo;
        kbase = (size_t)split * KSPL;
    } else {
        int u = bx - F_ITEMS;
        int tile = u >> 3; split = u & (NSPU - 1);
        if (tile * 128 >= cU) return;
        j0 = tile * 128; slotBase = UBASE + j0; list = g_listU; cnt = cU;
        bh = g_eMhi; bl = g_eMlo;
        kbase = (size_t)N_USER + (size_t)split * KSPL;
    }

    if (tid < 128) {
        int j = j0 + tid; if (j >= cnt) j = cnt - 1;
        sRow[tid] = adj + (size_t)list[j] * NTOT + kbase;
    }
    __syncthreads();

    // ---- A staging map ----
    int r0s = tid >> 3, chs = tid & 7;
    const float* apj[4];
#pragma unroll
    for (int j = 0; j < 4; ++j) apj[j] = sRow[r0s + 32 * j] + chs * 4;
    uint32_t aDst = smb + A_OFF + (uint32_t)(r0s * ASTR + chs * 4) * 4;

    // ---- B staging map ----
    int bn = tid >> 2, bc = tid & 3;
    const __nv_bfloat16* bsrcH = bh + kbase + (size_t)bn * NTOT + bc * 8;
    const __nv_bfloat16* bsrcL = bl + kbase + (size_t)bn * NTOT + bc * 8;
    uint32_t bDstH = smb + BH_OFF + (uint32_t)(bn * BSTR + bc * 8) * 2;
    uint32_t bDstL = smb + BL_OFF + (uint32_t)(bn * BSTR + bc * 8) * 2;

    // ---- compute-side addressing: warp tile = 32 rows x 32 cols ----
    int mg = wid >> 1;
    int nh = wid & 1;
    const float* aBase = (const float*)(sm + A_OFF);
    int frow0 = mg * 32 + (lane >> 2);
    const float* aR0 = aBase + frow0 * ASTR + (lane & 3) * 2;
    const float* aR1 = aR0 + 8 * ASTR;
    const float* aR2 = aR0 + 16 * ASTR;
    const float* aR3 = aR0 + 24 * ASTR;
    uint32_t bLm = (uint32_t)(((nh * 32 + (lane & 7) + ((lane >> 4) << 3)) * BSTR
                               + ((lane >> 3) & 1) * 8) * 2);

    float acc[2][4][4];
#pragma unroll
    for (int mb = 0; mb < 2; ++mb)
#pragma unroll
        for (int nb = 0; nb < 4; ++nb)
#pragma unroll
            for (int i = 0; i < 4; ++i) acc[mb][nb][i] = 0.f;

    // ---- prologue: stages 0,1 ----
#pragma unroll
    for (int s = 0; s < 2; ++s) {
        uint32_t ad = aDst + s * ASTAGE;
        size_t ko = (size_t)s * KT;
#pragma unroll
        for (int j = 0; j < 4; ++j) cp16cg(ad + j * (32 * ASTR * 4), apj[j] + ko);
        cp16cg(bDstH + s * BSTAGE, bsrcH + ko);
        cp16cg(bDstL + s * BSTAGE, bsrcL + ko);
        CP_COMMIT();
    }

    for (int kt = 0; kt < NKT; ++kt) {
        int buf = kt % NSTAGE;
        CP_WAIT(1);
        __syncthreads();
        if (kt + 2 < NKT) {
            int s = (kt + 2) % NSTAGE;
            uint32_t ad = aDst + s * ASTAGE;
            size_t ko = (size_t)(kt + 2) * KT;
#pragma unroll
            for (int j = 0; j < 4; ++j) cp16cg(ad + j * (32 * ASTR * 4), apj[j] + ko);
            cp16cg(bDstH + s * BSTAGE, bsrcH + ko);
            cp16cg(bDstL + s * BSTAGE, bsrcL + ko);
        }
        CP_COMMIT();

        int abufo = buf * (ASTAGE / 4);
        uint32_t bh_base = smb + BH_OFF + buf * BSTAGE + bLm;
        uint32_t bl_base = smb + BL_OFF + buf * BSTAGE + bLm;

#pragma unroll
        for (int ks = 0; ks < 2; ++ks) {
            int ko = ks * 16;
            uint32_t ahf[2][4], alf[2][4];
            {
                float2 x0 = *(const float2*)(aR0 + abufo + ko);
                float2 x1 = *(const float2*)(aR1 + abufo + ko);
                float2 x2 = *(const float2*)(aR0 + abufo + ko + 8);
                float2 x3 = *(const float2*)(aR1 + abufo + ko + 8);
                split2(x0, ahf[0][0], alf[0][0]);
                split2(x1, ahf[0][1], alf[0][1]);
                split2(x2, ahf[0][2], alf[0][2]);
                split2(x3, ahf[0][3], alf[0][3]);
                x0 = *(const float2*)(aR2 + abufo + ko);
                x1 = *(const float2*)(aR3 + abufo + ko);
                x2 = *(const float2*)(aR2 + abufo + ko + 8);
                x3 = *(const float2*)(aR3 + abufo + ko + 8);
                split2(x0, ahf[1][0], alf[1][0]);
                split2(x1, ahf[1][1], alf[1][1]);
                split2(x2, ahf[1][2], alf[1][2]);
                split2(x3, ahf[1][3], alf[1][3]);
            }
            uint32_t bhf[4][2], blf[4][2];
            {
                uint32_t r[4];
                ldmx4(r, bh_base + ks * 32);
                bhf[0][0] = r[0]; bhf[0][1] = r[1]; bhf[1][0] = r[2]; bhf[1][1] = r[3];
                ldmx4(r, bh_base + 16 * BSTR * 2 + ks * 32);
                bhf[2][0] = r[0]; bhf[2][1] = r[1]; bhf[3][0] = r[2]; bhf[3][1] = r[3];
                ldmx4(r, bl_base + ks * 32);
                blf[0][0] = r[0]; blf[0][1] = r[1]; blf[1][0] = r[2]; blf[1][1] = r[3];
                ldmx4(r, bl_base + 16 * BSTR * 2 + ks * 32);
                blf[2][0] = r[0]; blf[2][1] = r[1]; blf[3][0] = r[2]; blf[3][1] = r[3];
            }
#pragma unroll
            for (int mb = 0; mb < 2; ++mb)
#pragma unroll
                for (int nb = 0; nb < 4; ++nb) {
                    mma16816(acc[mb][nb], ahf[mb], bhf[nb]);
                    mma16816(acc[mb][nb], ahf[mb], blf[nb]);
                    mma16816(acc[mb][nb], alf[mb], bhf[nb]);
                }
        }
    }

    float* dst = g_part[split];
#pragma unroll
    for (int mb = 0; mb < 2; ++mb) {
        int r0 = slotBase + mg * 32 + mb * 16 + (lane >> 2);
#pragma unroll
        for (int nb = 0; nb < 4; ++nb) {
            int col = nh * 32 + nb * 8 + (lane & 3) * 2;
            *(float2*)(dst + (size_t)r0 * D + col)       = make_float2(acc[mb][nb][0], acc[mb][nb][1]);
            *(float2*)(dst + (size_t)(r0 + 8) * D + col) = make_float2(acc[mb][nb][2], acc[mb][nb][3]);
        }
    }
}

// -------- 4. gather: float4 per thread, deterministic reduction + rank-1 term --------
__global__ void k_gather(const float* __restrict__ adj,
                         const int* __restrict__ users, const int* __restrict__ pos,
                         const int* __restrict__ neg, float* __restrict__ out) {
    int t = blockIdx.x * 256 + threadIdx.x;    // t < 12288 * 16
    int q = t >> 4, ds = (t & 15) * 4;
    int r;
    if (q < BATCH)          r = users[q];
    else if (q < 2 * BATCH) r = N_USER + pos[q - BATCH];
    else                    r = N_USER + neg[q - 2 * BATCH];
    int p = g_pos[r];
    size_t o = (size_t)p * D + ds;
    float4 s = make_float4(0.f, 0.f, 0.f, 0.f);
    if (p < UBASE) {
#pragma unroll
        for (int k = 0; k < NSPF; ++k) {
            float4 v = *(const float4*)(g_part[k] + o);
            s.x += v.x; s.y += v.y; s.z += v.z; s.w += v.w;
        }
    } else {
#pragma unroll
        for (int k = 0; k < NSPU; ++k) {
            float4 v = *(const float4*)(g_part[k] + o);
            s.x += v.x; s.y += v.y; s.z += v.z; s.w += v.w;
        }
        int u0 = users[0];
        float a = adj[(size_t)r * NTOT + u0];
        float4 e0 = *(const float4*)(g_ego + (size_t)u0 * D + ds);
        s.x += a * e0.x; s.y += a * e0.y; s.z += a * e0.z; s.w += a * e0.w;
    }
    float4 eg = *(const float4*)(g_ego + (size_t)r * D + ds);
    float4 res;
    res.x = 0.25f * (eg.x + 3.0f * s.x);
    res.y = 0.25f * (eg.y + 3.0f * s.y);
    res.z = 0.25f * (eg.z + 3.0f * s.z);
    res.w = 0.25f * (eg.w + 3.0f * s.w);
    *(float4*)(out + (size_t)q * D + ds) = res;
}

extern "C" void kernel_launch(void* const* d_in, const int* in_sizes, int n_in,
                              void* d_out, int out_size) {
    const float* adj   = (const float*)d_in[0];
    const float* ue    = (const float*)d_in[1];
    const float* ie    = (const float*)d_in[2];
    const int*   users = (const int*)d_in[3];
    const int*   pos   = (const int*)d_in[4];
    const int*   neg   = (const int*)d_in[5];
    float*       out   = (float*)d_out;

    cudaFuncSetAttribute(k_main, cudaFuncAttributeMaxDynamicSharedMemorySize, SM_TOTAL);

    k_compact<<<1, 1024>>>(users, pos, neg);
    k_pre<<<NTOT / 64, 256>>>(ue, ie);
    k_main<<<F_ITEMS + U_ITEMS, 256, SM_TOTAL>>>(adj);
    k_gather<<<(6 * BATCH * D / 4) / 256, 256>>>(adj, users, pos, neg, out);
}